// round 1
// baseline (speedup 1.0000x reference)
#include <cuda_runtime.h>
#include <cmath>

#define SQ 4096
#define DM 512
#define HH 8
#define DKH 64

// Intermediate scratch (device globals: no allocation allowed in kernel_launch)
__device__ float g_q[SQ * DM];
__device__ float g_k[SQ * DM];
__device__ float g_v[SQ * DM];
__device__ float g_attn[SQ * DM];
__device__ unsigned g_maskbits[SQ * (SQ / 32)];  // 2 MB packed mask

// ---------------------------------------------------------------------------
// Pack int32 mask (0/1) into bits. bit index = q*4096 + k  (flat order).
// One warp produces one 32-bit word via ballot.
// ---------------------------------------------------------------------------
__global__ void mask_pack_kernel(const int* __restrict__ mask) {
    int gw = blockIdx.x * (blockDim.x >> 5) + (threadIdx.x >> 5);
    int lane = threadIdx.x & 31;
    unsigned b = __ballot_sync(0xffffffffu, mask[gw * 32 + lane] != 0);
    if (lane == 0) g_maskbits[gw] = b;
}

// ---------------------------------------------------------------------------
// C[M,512] = A[M,512] @ B[512,512]^T + bias   (NT gemm, K=N=512 hardcoded)
// 64x64 block tile, BK=16, 4x4 per thread, 256 threads.
// ---------------------------------------------------------------------------
__global__ void __launch_bounds__(256) gemm512(const float* __restrict__ A,
                                               const float* __restrict__ B,
                                               const float* __restrict__ bias,
                                               float* __restrict__ C) {
    __shared__ float sA[16][68];  // [k][m], pad 4 keeps float4 alignment
    __shared__ float sB[16][68];  // [k][n]
    int tid = threadIdx.x;
    int tx = tid & 15, ty = tid >> 4;
    int m0 = blockIdx.y * 64, n0 = blockIdx.x * 64;
    int lr = tid >> 2;          // 0..63
    int lc = (tid & 3) << 2;    // 0,4,8,12

    const float* Ap = A + (m0 + lr) * 512 + lc;
    const float* Bp = B + (n0 + lr) * 512 + lc;

    float acc[4][4] = {};

    for (int k0 = 0; k0 < 512; k0 += 16) {
        float4 av = *(const float4*)(Ap + k0);
        float4 bv = *(const float4*)(Bp + k0);
        __syncthreads();
        sA[lc + 0][lr] = av.x; sA[lc + 1][lr] = av.y;
        sA[lc + 2][lr] = av.z; sA[lc + 3][lr] = av.w;
        sB[lc + 0][lr] = bv.x; sB[lc + 1][lr] = bv.y;
        sB[lc + 2][lr] = bv.z; sB[lc + 3][lr] = bv.w;
        __syncthreads();
#pragma unroll
        for (int kk = 0; kk < 16; kk++) {
            float4 a4 = *(const float4*)&sA[kk][ty << 2];
            float4 b4 = *(const float4*)&sB[kk][tx << 2];
            float aa[4] = {a4.x, a4.y, a4.z, a4.w};
            float bb[4] = {b4.x, b4.y, b4.z, b4.w};
#pragma unroll
            for (int i = 0; i < 4; i++)
#pragma unroll
                for (int j = 0; j < 4; j++) acc[i][j] += aa[i] * bb[j];
        }
    }

#pragma unroll
    for (int i = 0; i < 4; i++) {
        int row = m0 + (ty << 2) + i;
#pragma unroll
        for (int j = 0; j < 4; j++) {
            int col = n0 + (tx << 2) + j;
            C[row * 512 + col] = acc[i][j] + bias[col];
        }
    }
}

// ---------------------------------------------------------------------------
// Flash attention, fp32. One block = one (q-tile of 64, head).
// Head h of Q/K/V = contiguous 4096x64 chunk at offset h*4096*64 (faithful
// buggy reshape). Output written at attn[s', h*64+dk].
// ---------------------------------------------------------------------------
#define SM_QT 0
#define SM_KT 4352            // 64*68
#define SM_P  8704
#define SM_V  13056
#define SM_MASK 17152         // (in floats) then 128 unsigned words
#define ATTN_SMEM_BYTES (17152 * 4 + 128 * 4)

__global__ void __launch_bounds__(256) attn_kernel() {
    extern __shared__ float sm[];
    float(*sQt)[68] = (float(*)[68])(sm + SM_QT);   // [d][r]
    float(*sKt)[68] = (float(*)[68])(sm + SM_KT);   // [d][c]
    float(*sP)[68]  = (float(*)[68])(sm + SM_P);    // [r][k]
    float(*sV)[64]  = (float(*)[64])(sm + SM_V);    // [k][d]
    unsigned* sMask = (unsigned*)(sm + SM_MASK);    // [r][2] words

    int tid = threadIdx.x;
    int tx = tid & 15, ty = tid >> 4;
    int qt = blockIdx.x, h = blockIdx.y;

    const float* Qh = g_q + h * (SQ * DKH);
    const float* Kh = g_k + h * (SQ * DKH);
    const float* Vh = g_v + h * (SQ * DKH);

    int lr = tid >> 2;          // 0..63  (row within tile for loads)
    int lc = (tid & 3) << 4;    // 0,16,32,48 (d-chunk base)

    // Load Q tile transposed: sQt[d][r]
    {
        const float* qrow = Qh + (qt * 64 + lr) * 64 + lc;
#pragma unroll
        for (int v = 0; v < 4; v++) {
            float4 q4 = *(const float4*)(qrow + v * 4);
            sQt[lc + v * 4 + 0][lr] = q4.x;
            sQt[lc + v * 4 + 1][lr] = q4.y;
            sQt[lc + v * 4 + 2][lr] = q4.z;
            sQt[lc + v * 4 + 3][lr] = q4.w;
        }
    }

    float m_i[4], l_i[4], o[4][4];
#pragma unroll
    for (int i = 0; i < 4; i++) {
        m_i[i] = -INFINITY;
        l_i[i] = 0.f;
#pragma unroll
        for (int j = 0; j < 4; j++) o[i][j] = 0.f;
    }

    for (int kt = 0; kt < 64; kt++) {
        __syncthreads();  // previous iteration's P@V done before overwrite
        {
            const float* krow = Kh + (kt * 64 + lr) * 64 + lc;
            const float* vrow = Vh + (kt * 64 + lr) * 64 + lc;
#pragma unroll
            for (int v = 0; v < 4; v++) {
                float4 k4 = *(const float4*)(krow + v * 4);
                sKt[lc + v * 4 + 0][lr] = k4.x;
                sKt[lc + v * 4 + 1][lr] = k4.y;
                sKt[lc + v * 4 + 2][lr] = k4.z;
                sKt[lc + v * 4 + 3][lr] = k4.w;
                float4 v4 = *(const float4*)(vrow + v * 4);
                *(float4*)&sV[lr][lc + v * 4] = v4;
            }
            if (tid < 128) {
                int r = tid >> 1, w = tid & 1;
                sMask[tid] = g_maskbits[(qt * 64 + r) * 128 + kt * 2 + w];
            }
        }
        __syncthreads();

        // S = Q @ K^T for this thread's 4x4 block
        float sc[4][4] = {};
#pragma unroll 16
        for (int d = 0; d < 64; d++) {
            float4 q4 = *(const float4*)&sQt[d][ty << 2];
            float4 k4 = *(const float4*)&sKt[d][tx << 2];
            float qa[4] = {q4.x, q4.y, q4.z, q4.w};
            float ka[4] = {k4.x, k4.y, k4.z, k4.w};
#pragma unroll
            for (int i = 0; i < 4; i++)
#pragma unroll
                for (int j = 0; j < 4; j++) sc[i][j] += qa[i] * ka[j];
        }

        // scale + mask + online softmax (row groups = 16 lanes sharing ty)
#pragma unroll
        for (int i = 0; i < 4; i++) {
            int rl = (ty << 2) + i;
            unsigned w0 = sMask[rl * 2 + 0];
            unsigned w1 = sMask[rl * 2 + 1];
            float rowm = -INFINITY;
            float p[4];
#pragma unroll
            for (int j = 0; j < 4; j++) {
                int c = (tx << 2) + j;
                float s = sc[i][j] * 0.125f;
                unsigned wb = (c & 32) ? w1 : w0;
                if ((wb >> (c & 31)) & 1u) s -= 1e9f;
                sc[i][j] = s;
                rowm = fmaxf(rowm, s);
            }
            rowm = fmaxf(rowm, __shfl_xor_sync(0xffffffffu, rowm, 1));
            rowm = fmaxf(rowm, __shfl_xor_sync(0xffffffffu, rowm, 2));
            rowm = fmaxf(rowm, __shfl_xor_sync(0xffffffffu, rowm, 4));
            rowm = fmaxf(rowm, __shfl_xor_sync(0xffffffffu, rowm, 8));
            float mn = fmaxf(m_i[i], rowm);
            float alpha = __expf(m_i[i] - mn);
            m_i[i] = mn;
            float rs = 0.f;
#pragma unroll
            for (int j = 0; j < 4; j++) {
                p[j] = __expf(sc[i][j] - mn);
                rs += p[j];
            }
            rs += __shfl_xor_sync(0xffffffffu, rs, 1);
            rs += __shfl_xor_sync(0xffffffffu, rs, 2);
            rs += __shfl_xor_sync(0xffffffffu, rs, 4);
            rs += __shfl_xor_sync(0xffffffffu, rs, 8);
            l_i[i] = l_i[i] * alpha + rs;
#pragma unroll
            for (int j = 0; j < 4; j++) o[i][j] *= alpha;
            *(float4*)&sP[rl][tx << 2] = make_float4(p[0], p[1], p[2], p[3]);
        }
        __syncthreads();

        // O += P @ V
#pragma unroll 8
        for (int k = 0; k < 64; k++) {
            float4 v4 = *(const float4*)&sV[k][tx << 2];
            float va[4] = {v4.x, v4.y, v4.z, v4.w};
#pragma unroll
            for (int i = 0; i < 4; i++) {
                float pik = sP[(ty << 2) + i][k];
                o[i][0] += pik * va[0];
                o[i][1] += pik * va[1];
                o[i][2] += pik * va[2];
                o[i][3] += pik * va[3];
            }
        }
    }

    // epilogue: normalize, write attn[s', h*64 + dk]
#pragma unroll
    for (int i = 0; i < 4; i++) {
        float inv = 1.f / l_i[i];
        int srow = qt * 64 + (ty << 2) + i;
        float4 ov = make_float4(o[i][0] * inv, o[i][1] * inv, o[i][2] * inv,
                                o[i][3] * inv);
        *(float4*)&g_attn[srow * 512 + h * 64 + (tx << 2)] = ov;
    }
}

// ---------------------------------------------------------------------------
extern "C" void kernel_launch(void* const* d_in, const int* in_sizes, int n_in,
                              void* d_out, int out_size) {
    const float* x    = (const float*)d_in[0];
    const int*   mask = (const int*)d_in[1];
    const float* wq_w = (const float*)d_in[2];
    const float* wq_b = (const float*)d_in[3];
    const float* wk_w = (const float*)d_in[4];
    const float* wk_b = (const float*)d_in[5];
    const float* wv_w = (const float*)d_in[6];
    const float* wv_b = (const float*)d_in[7];
    const float* dw   = (const float*)d_in[8];
    const float* db   = (const float*)d_in[9];
    float* out = (float*)d_out;

    float *qp, *kp, *vp, *ap;
    cudaGetSymbolAddress((void**)&qp, g_q);
    cudaGetSymbolAddress((void**)&kp, g_k);
    cudaGetSymbolAddress((void**)&vp, g_v);
    cudaGetSymbolAddress((void**)&ap, g_attn);

    cudaFuncSetAttribute(attn_kernel,
                         cudaFuncAttributeMaxDynamicSharedMemorySize,
                         ATTN_SMEM_BYTES);

    // 524288 mask words, 8 warps per block -> 65536 blocks
    mask_pack_kernel<<<SQ * SQ / 32 / 8, 256>>>(mask);

    dim3 gg(512 / 64, 4096 / 64);
    gemm512<<<gg, 256>>>(x, wq_w, wq_b, qp);
    gemm512<<<gg, 256>>>(x, wk_w, wk_b, kp);
    gemm512<<<gg, 256>>>(x, wv_w, wv_b, vp);

    attn_kernel<<<dim3(64, 8), 256, ATTN_SMEM_BYTES>>>();

    gemm512<<<gg, 256>>>(ap, dw, db, out);
}

// round 3
// speedup vs baseline: 2.1939x; 2.1939x over previous
#include <cuda_runtime.h>
#include <cmath>

#define SQ 4096
#define DM 512
#define HH 8
#define DKH 64

// Intermediate scratch (device globals: no allocation allowed)
__device__ float g_q[SQ * DM];
__device__ float g_k[SQ * DM];
__device__ float g_v[SQ * DM];
__device__ float g_attn[SQ * DM];
__device__ unsigned g_maskbits[SQ * (SQ / 32)];  // 2 MB packed mask

// ---------------------------------------------------------------------------
// Pack int32 mask (0/1) into bits. bit index = q*4096 + k.
// ---------------------------------------------------------------------------
__global__ void mask_pack_kernel(const int* __restrict__ mask) {
    int gw = blockIdx.x * (blockDim.x >> 5) + (threadIdx.x >> 5);
    int lane = threadIdx.x & 31;
    unsigned b = __ballot_sync(0xffffffffu, mask[gw * 32 + lane] != 0);
    if (lane == 0) g_maskbits[gw] = b;
}

// ---------------------------------------------------------------------------
// C[M,512] = A[M,512] @ B[512,512]^T + bias   (fp32 NT gemm)
// ---------------------------------------------------------------------------
__global__ void __launch_bounds__(256) gemm512(const float* __restrict__ A,
                                               const float* __restrict__ B,
                                               const float* __restrict__ bias,
                                               float* __restrict__ C) {
    __shared__ float sA[16][68];
    __shared__ float sB[16][68];
    int tid = threadIdx.x;
    int tx = tid & 15, ty = tid >> 4;
    int m0 = blockIdx.y * 64, n0 = blockIdx.x * 64;
    int lr = tid >> 2;
    int lc = (tid & 3) << 2;

    const float* Ap = A + (m0 + lr) * 512 + lc;
    const float* Bp = B + (n0 + lr) * 512 + lc;

    float acc[4][4] = {};

    for (int k0 = 0; k0 < 512; k0 += 16) {
        float4 av = *(const float4*)(Ap + k0);
        float4 bv = *(const float4*)(Bp + k0);
        __syncthreads();
        sA[lc + 0][lr] = av.x; sA[lc + 1][lr] = av.y;
        sA[lc + 2][lr] = av.z; sA[lc + 3][lr] = av.w;
        sB[lc + 0][lr] = bv.x; sB[lc + 1][lr] = bv.y;
        sB[lc + 2][lr] = bv.z; sB[lc + 3][lr] = bv.w;
        __syncthreads();
#pragma unroll
        for (int kk = 0; kk < 16; kk++) {
            float4 a4 = *(const float4*)&sA[kk][ty << 2];
            float4 b4 = *(const float4*)&sB[kk][tx << 2];
            float aa[4] = {a4.x, a4.y, a4.z, a4.w};
            float bb[4] = {b4.x, b4.y, b4.z, b4.w};
#pragma unroll
            for (int i = 0; i < 4; i++)
#pragma unroll
                for (int j = 0; j < 4; j++) acc[i][j] += aa[i] * bb[j];
        }
    }

#pragma unroll
    for (int i = 0; i < 4; i++) {
        int row = m0 + (ty << 2) + i;
#pragma unroll
        for (int j = 0; j < 4; j++) {
            int col = n0 + (tx << 2) + j;
            C[row * 512 + col] = acc[i][j] + bias[col];
        }
    }
}

// ---------------------------------------------------------------------------
// Tensor-core flash attention (tf32 mma.sync, fp32 accumulate).
// Block = 128 q-rows x 1 head. 8 warps, each owns 16 q-rows. BK = 64.
// ---------------------------------------------------------------------------
#define PITCH 68
#define SM_K 0
#define SM_V (64 * PITCH)
#define SM_P (2 * 64 * PITCH)
#define SM_Q (SM_P + 8 * 16 * PITCH)
#define ATTN_SMEM_U (SM_Q + 128 * PITCH)
#define ATTN_SMEM_BYTES (ATTN_SMEM_U * 4)

__device__ __forceinline__ unsigned f2tf(float f) {
    unsigned u;
    asm("cvt.rna.tf32.f32 %0, %1;" : "=r"(u) : "f"(f));
    return u;
}

__device__ __forceinline__ void mma8(float* d, const unsigned* a, unsigned b0,
                                     unsigned b1) {
    asm volatile(
        "mma.sync.aligned.m16n8k8.row.col.f32.tf32.tf32.f32 "
        "{%0,%1,%2,%3},{%4,%5,%6,%7},{%8,%9},{%0,%1,%2,%3};"
        : "+f"(d[0]), "+f"(d[1]), "+f"(d[2]), "+f"(d[3])
        : "r"(a[0]), "r"(a[1]), "r"(a[2]), "r"(a[3]), "r"(b0), "r"(b1));
}

__global__ void __launch_bounds__(256, 2) attn_tc_kernel() {
    extern __shared__ unsigned smu[];
    unsigned(*sK)[PITCH] = (unsigned(*)[PITCH])(smu + SM_K);   // [key][d]
    unsigned(*sV)[PITCH] = (unsigned(*)[PITCH])(smu + SM_V);   // [key][d]
    unsigned(*sQ)[PITCH] = (unsigned(*)[PITCH])(smu + SM_Q);   // [qrow][d]

    int tid = threadIdx.x;
    int w = tid >> 5, lane = tid & 31;
    int t4 = lane >> 2, tm4 = lane & 3;
    int qt = blockIdx.x, h = blockIdx.y;

    const float* Qh = g_q + h * (SQ * DKH);
    const float* Kh = g_k + h * (SQ * DKH);
    const float* Vh = g_v + h * (SQ * DKH);

    unsigned(*sP)[PITCH] = (unsigned(*)[PITCH])(smu + SM_P + w * 16 * PITCH);

    // Stage Q (scale folded, tf32-rounded)
#pragma unroll
    for (int i = 0; i < 8; i++) {
        int idx = tid + i * 256;
        int row = idx >> 4, c4 = (idx & 15) << 2;
        float4 q4 = *(const float4*)(Qh + (qt * 128 + row) * 64 + c4);
        sQ[row][c4 + 0] = f2tf(q4.x * 0.125f);
        sQ[row][c4 + 1] = f2tf(q4.y * 0.125f);
        sQ[row][c4 + 2] = f2tf(q4.z * 0.125f);
        sQ[row][c4 + 3] = f2tf(q4.w * 0.125f);
    }

    float o[8][4];
#pragma unroll
    for (int nt = 0; nt < 8; nt++)
#pragma unroll
        for (int j = 0; j < 4; j++) o[nt][j] = 0.f;
    float m0 = -INFINITY, m1 = -INFINITY, l0 = 0.f, l1 = 0.f;

    const unsigned* mrow0 = g_maskbits + (qt * 128 + w * 16 + t4) * 128;
    const unsigned* mrow1 = mrow0 + 8 * 128;

    for (int kt = 0; kt < 64; kt++) {
        __syncthreads();
        // Stage K, V tiles (tf32-rounded)
#pragma unroll
        for (int i = 0; i < 4; i++) {
            int idx = tid + i * 256;
            int row = idx >> 4, c4 = (idx & 15) << 2;
            const float* kp = Kh + (kt * 64 + row) * 64 + c4;
            const float* vp = Vh + (kt * 64 + row) * 64 + c4;
            float4 k4 = *(const float4*)kp;
            float4 v4 = *(const float4*)vp;
            sK[row][c4 + 0] = f2tf(k4.x); sK[row][c4 + 1] = f2tf(k4.y);
            sK[row][c4 + 2] = f2tf(k4.z); sK[row][c4 + 3] = f2tf(k4.w);
            sV[row][c4 + 0] = f2tf(v4.x); sV[row][c4 + 1] = f2tf(v4.y);
            sV[row][c4 + 2] = f2tf(v4.z); sV[row][c4 + 3] = f2tf(v4.w);
        }
        __syncthreads();

        // S = (Q/8) @ K^T   [16 x 64 per warp]
        float s[8][4];
#pragma unroll
        for (int nt = 0; nt < 8; nt++)
#pragma unroll
            for (int j = 0; j < 4; j++) s[nt][j] = 0.f;
#pragma unroll
        for (int kc = 0; kc < 8; kc++) {
            unsigned a[4];
            a[0] = sQ[w * 16 + t4][kc * 8 + tm4];
            a[1] = sQ[w * 16 + t4 + 8][kc * 8 + tm4];
            a[2] = sQ[w * 16 + t4][kc * 8 + tm4 + 4];
            a[3] = sQ[w * 16 + t4 + 8][kc * 8 + tm4 + 4];
#pragma unroll
            for (int nt = 0; nt < 8; nt++) {
                unsigned b0 = sK[nt * 8 + t4][kc * 8 + tm4];
                unsigned b1 = sK[nt * 8 + t4][kc * 8 + tm4 + 4];
                mma8(s[nt], a, b0, b1);
            }
        }

        // Mask + online softmax. Thread owns rows (t4, t4+8), cols nt*8+tm4*2+{0,1}
        unsigned mw0a = mrow0[kt * 2], mw0b = mrow0[kt * 2 + 1];
        unsigned mw1a = mrow1[kt * 2], mw1b = mrow1[kt * 2 + 1];
        float rmax0 = -INFINITY, rmax1 = -INFINITY;
#pragma unroll
        for (int nt = 0; nt < 8; nt++) {
            int c = nt * 8 + tm4 * 2;
            unsigned w0 = (c & 32) ? mw0b : mw0a;
            unsigned w1 = (c & 32) ? mw1b : mw1a;
            int sh = c & 31;
            if ((w0 >> sh) & 1u) s[nt][0] -= 1e9f;
            if ((w0 >> (sh + 1)) & 1u) s[nt][1] -= 1e9f;
            if ((w1 >> sh) & 1u) s[nt][2] -= 1e9f;
            if ((w1 >> (sh + 1)) & 1u) s[nt][3] -= 1e9f;
            rmax0 = fmaxf(rmax0, fmaxf(s[nt][0], s[nt][1]));
            rmax1 = fmaxf(rmax1, fmaxf(s[nt][2], s[nt][3]));
        }
        rmax0 = fmaxf(rmax0, __shfl_xor_sync(0xffffffffu, rmax0, 1));
        rmax0 = fmaxf(rmax0, __shfl_xor_sync(0xffffffffu, rmax0, 2));
        rmax1 = fmaxf(rmax1, __shfl_xor_sync(0xffffffffu, rmax1, 1));
        rmax1 = fmaxf(rmax1, __shfl_xor_sync(0xffffffffu, rmax1, 2));

        float mn0 = fmaxf(m0, rmax0), mn1 = fmaxf(m1, rmax1);
        float al0 = __expf(m0 - mn0), al1 = __expf(m1 - mn1);
        m0 = mn0; m1 = mn1;

        float rs0 = 0.f, rs1 = 0.f;
#pragma unroll
        for (int nt = 0; nt < 8; nt++) {
            float p00 = __expf(s[nt][0] - mn0);
            float p01 = __expf(s[nt][1] - mn0);
            float p10 = __expf(s[nt][2] - mn1);
            float p11 = __expf(s[nt][3] - mn1);
            rs0 += p00 + p01;
            rs1 += p10 + p11;
            uint2 u0; u0.x = f2tf(p00); u0.y = f2tf(p01);
            uint2 u1; u1.x = f2tf(p10); u1.y = f2tf(p11);
            *(uint2*)&sP[t4][nt * 8 + tm4 * 2] = u0;
            *(uint2*)&sP[t4 + 8][nt * 8 + tm4 * 2] = u1;
        }
        rs0 += __shfl_xor_sync(0xffffffffu, rs0, 1);
        rs0 += __shfl_xor_sync(0xffffffffu, rs0, 2);
        rs1 += __shfl_xor_sync(0xffffffffu, rs1, 1);
        rs1 += __shfl_xor_sync(0xffffffffu, rs1, 2);
        l0 = l0 * al0 + rs0;
        l1 = l1 * al1 + rs1;
#pragma unroll
        for (int nt = 0; nt < 8; nt++) {
            o[nt][0] *= al0; o[nt][1] *= al0;
            o[nt][2] *= al1; o[nt][3] *= al1;
        }
        __syncwarp();

        // O += P @ V
        unsigned pf[8][4];
#pragma unroll
        for (int kc = 0; kc < 8; kc++) {
            pf[kc][0] = sP[t4][kc * 8 + tm4];
            pf[kc][1] = sP[t4 + 8][kc * 8 + tm4];
            pf[kc][2] = sP[t4][kc * 8 + tm4 + 4];
            pf[kc][3] = sP[t4 + 8][kc * 8 + tm4 + 4];
        }
#pragma unroll
        for (int kc = 0; kc < 8; kc++)
#pragma unroll
            for (int nt = 0; nt < 8; nt++) {
                unsigned b0 = sV[kc * 8 + tm4][nt * 8 + t4];
                unsigned b1 = sV[kc * 8 + tm4 + 4][nt * 8 + t4];
                mma8(o[nt], pf[kc], b0, b1);
            }
    }

    // Epilogue: normalize, write attn[s', h*64 + d]
    float inv0 = 1.f / l0, inv1 = 1.f / l1;
    int r0 = qt * 128 + w * 16 + t4;
    int r1 = r0 + 8;
#pragma unroll
    for (int nt = 0; nt < 8; nt++) {
        int c = h * 64 + nt * 8 + tm4 * 2;
        float2 v0 = make_float2(o[nt][0] * inv0, o[nt][1] * inv0);
        float2 v1 = make_float2(o[nt][2] * inv1, o[nt][3] * inv1);
        *(float2*)&g_attn[r0 * 512 + c] = v0;
        *(float2*)&g_attn[r1 * 512 + c] = v1;
    }
}

// ---------------------------------------------------------------------------
extern "C" void kernel_launch(void* const* d_in, const int* in_sizes, int n_in,
                              void* d_out, int out_size) {
    const float* x    = (const float*)d_in[0];
    const int*   mask = (const int*)d_in[1];
    const float* wq_w = (const float*)d_in[2];
    const float* wq_b = (const float*)d_in[3];
    const float* wk_w = (const float*)d_in[4];
    const float* wk_b = (const float*)d_in[5];
    const float* wv_w = (const float*)d_in[6];
    const float* wv_b = (const float*)d_in[7];
    const float* dw   = (const float*)d_in[8];
    const float* db   = (const float*)d_in[9];
    float* out = (float*)d_out;

    float *qp, *kp, *vp, *ap;
    cudaGetSymbolAddress((void**)&qp, g_q);
    cudaGetSymbolAddress((void**)&kp, g_k);
    cudaGetSymbolAddress((void**)&vp, g_v);
    cudaGetSymbolAddress((void**)&ap, g_attn);

    cudaFuncSetAttribute(attn_tc_kernel,
                         cudaFuncAttributeMaxDynamicSharedMemorySize,
                         ATTN_SMEM_BYTES);

    mask_pack_kernel<<<SQ * SQ / 32 / 8, 256>>>(mask);

    dim3 gg(512 / 64, 4096 / 64);
    gemm512<<<gg, 256>>>(x, wq_w, wq_b, qp);
    gemm512<<<gg, 256>>>(x, wk_w, wk_b, kp);
    gemm512<<<gg, 256>>>(x, wv_w, wv_b, vp);

    attn_tc_kernel<<<dim3(32, 8), 256, ATTN_SMEM_BYTES>>>();

    gemm512<<<gg, 256>>>(ap, dw, db, out);
}

// round 6
// speedup vs baseline: 3.0056x; 1.3700x over previous
#include <cuda_runtime.h>
#include <cmath>

#define SQ 4096
#define DM 512
#define HH 8
#define DKH 64

// Intermediate scratch (device globals: no allocation allowed)
__device__ float g_q[SQ * DM];
__device__ float g_k[SQ * DM];
__device__ float g_v[SQ * DM];
__device__ float g_attn[SQ * DM];
__device__ unsigned g_maskbits[SQ * (SQ / 32)];  // 2 MB packed mask

__device__ __forceinline__ unsigned f2tf(float f) {
    unsigned u;
    asm("cvt.rna.tf32.f32 %0, %1;" : "=r"(u) : "f"(f));
    return u;
}

__device__ __forceinline__ void mma8(float* d, const unsigned* a, unsigned b0,
                                     unsigned b1) {
    asm volatile(
        "mma.sync.aligned.m16n8k8.row.col.f32.tf32.tf32.f32 "
        "{%0,%1,%2,%3},{%4,%5,%6,%7},{%8,%9},{%0,%1,%2,%3};"
        : "+f"(d[0]), "+f"(d[1]), "+f"(d[2]), "+f"(d[3])
        : "r"(a[0]), "r"(a[1]), "r"(a[2]), "r"(a[3]), "r"(b0), "r"(b1));
}

// ---------------------------------------------------------------------------
// Pack int32 mask (0/1) into bits. bit index = q*4096 + k.
// ---------------------------------------------------------------------------
__global__ void mask_pack_kernel(const int* __restrict__ mask) {
    int gw = blockIdx.x * (blockDim.x >> 5) + (threadIdx.x >> 5);
    int lane = threadIdx.x & 31;
    unsigned b = __ballot_sync(0xffffffffu, mask[gw * 32 + lane] != 0);
    if (lane == 0) g_maskbits[gw] = b;
}

// Dummy: shifts attention into ncu's -s 5 -c 1 capture slot.
__global__ void dummy_kernel() {}

// ---------------------------------------------------------------------------
// tf32 tensor-core GEMM: C[4096,512] = A[4096,512] @ B[512,512]^T + bias
// Block tile 128m x 64n, BK=32, 8 warps (4m x 2n), 32x32 warp tile.
// ---------------------------------------------------------------------------
#define GPITCH 36

__global__ void __launch_bounds__(256) gemm_tf32(const float* __restrict__ A,
                                                 const float* __restrict__ B,
                                                 const float* __restrict__ bias,
                                                 float* __restrict__ C) {
    __shared__ unsigned sA[128][GPITCH];
    __shared__ unsigned sB[64][GPITCH];

    int tid = threadIdx.x;
    int w = tid >> 5, lane = tid & 31;
    int t4 = lane >> 2, tm4 = lane & 3;
    int wm = (w >> 1) * 32, wn = (w & 1) * 32;
    int m0 = blockIdx.y * 128, n0 = blockIdx.x * 64;

    // load indexing: A tile 128x32 = 1024 float4 (4 per thread), B 64x32 = 512 (2)
    int ar[4], ac4[4], br[2], bc4[2];
#pragma unroll
    for (int i = 0; i < 4; i++) {
        int idx = tid + i * 256;
        ar[i] = idx >> 3;
        ac4[i] = (idx & 7) << 2;
    }
#pragma unroll
    for (int i = 0; i < 2; i++) {
        int idx = tid + i * 256;
        br[i] = idx >> 3;
        bc4[i] = (idx & 7) << 2;
    }

    float4 aR[4], bR[2];
#pragma unroll
    for (int i = 0; i < 4; i++)
        aR[i] = *(const float4*)(A + (m0 + ar[i]) * 512 + ac4[i]);
#pragma unroll
    for (int i = 0; i < 2; i++)
        bR[i] = *(const float4*)(B + (n0 + br[i]) * 512 + bc4[i]);

    float acc[2][4][4] = {};

    for (int k0 = 0; k0 < 512; k0 += 32) {
        // store staged regs -> smem (tf32 convert, 128-bit stores)
#pragma unroll
        for (int i = 0; i < 4; i++) {
            uint4 u;
            u.x = f2tf(aR[i].x); u.y = f2tf(aR[i].y);
            u.z = f2tf(aR[i].z); u.w = f2tf(aR[i].w);
            *(uint4*)&sA[ar[i]][ac4[i]] = u;
        }
#pragma unroll
        for (int i = 0; i < 2; i++) {
            uint4 u;
            u.x = f2tf(bR[i].x); u.y = f2tf(bR[i].y);
            u.z = f2tf(bR[i].z); u.w = f2tf(bR[i].w);
            *(uint4*)&sB[br[i]][bc4[i]] = u;
        }
        __syncthreads();

        // prefetch next k-slab while mma runs
        if (k0 + 32 < 512) {
#pragma unroll
            for (int i = 0; i < 4; i++)
                aR[i] = *(const float4*)(A + (m0 + ar[i]) * 512 + k0 + 32 + ac4[i]);
#pragma unroll
            for (int i = 0; i < 2; i++)
                bR[i] = *(const float4*)(B + (n0 + br[i]) * 512 + k0 + 32 + bc4[i]);
        }

#pragma unroll
        for (int kc = 0; kc < 4; kc++) {
            unsigned a[2][4];
#pragma unroll
            for (int i = 0; i < 2; i++) {
                int r = wm + i * 16;
                a[i][0] = sA[r + t4][kc * 8 + tm4];
                a[i][1] = sA[r + t4 + 8][kc * 8 + tm4];
                a[i][2] = sA[r + t4][kc * 8 + tm4 + 4];
                a[i][3] = sA[r + t4 + 8][kc * 8 + tm4 + 4];
            }
#pragma unroll
            for (int j = 0; j < 4; j++) {
                unsigned b0 = sB[wn + j * 8 + t4][kc * 8 + tm4];
                unsigned b1 = sB[wn + j * 8 + t4][kc * 8 + tm4 + 4];
                mma8(acc[0][j], a[0], b0, b1);
                mma8(acc[1][j], a[1], b0, b1);
            }
        }
        __syncthreads();
    }

    // epilogue: add bias, write
#pragma unroll
    for (int i = 0; i < 2; i++) {
        int r0 = m0 + wm + i * 16 + t4;
#pragma unroll
        for (int j = 0; j < 4; j++) {
            int c = n0 + wn + j * 8 + tm4 * 2;
            float b0 = bias[c], b1 = bias[c + 1];
            *(float2*)&C[r0 * 512 + c] =
                make_float2(acc[i][j][0] + b0, acc[i][j][1] + b1);
            *(float2*)&C[(r0 + 8) * 512 + c] =
                make_float2(acc[i][j][2] + b0, acc[i][j][3] + b1);
        }
    }
}

// ---------------------------------------------------------------------------
// Tensor-core flash attention (tf32 mma.sync, fp32 accumulate).
// Block = 128 q-rows x 1 head. 8 warps, each owns 16 q-rows. BK = 64.
// ---------------------------------------------------------------------------
#define PITCH 68
#define SM_K 0
#define SM_V (64 * PITCH)
#define SM_P (2 * 64 * PITCH)
#define SM_Q (SM_P + 8 * 16 * PITCH)
#define ATTN_SMEM_U (SM_Q + 128 * PITCH)
#define ATTN_SMEM_BYTES (ATTN_SMEM_U * 4)

__global__ void __launch_bounds__(256, 2) attn_tc_kernel() {
    extern __shared__ unsigned smu[];
    unsigned(*sK)[PITCH] = (unsigned(*)[PITCH])(smu + SM_K);   // [key][d]
    unsigned(*sV)[PITCH] = (unsigned(*)[PITCH])(smu + SM_V);   // [key][d]
    unsigned(*sQ)[PITCH] = (unsigned(*)[PITCH])(smu + SM_Q);   // [qrow][d]

    int tid = threadIdx.x;
    int w = tid >> 5, lane = tid & 31;
    int t4 = lane >> 2, tm4 = lane & 3;
    int qt = blockIdx.x, h = blockIdx.y;

    const float* Qh = g_q + h * (SQ * DKH);
    const float* Kh = g_k + h * (SQ * DKH);
    const float* Vh = g_v + h * (SQ * DKH);

    unsigned(*sP)[PITCH] = (unsigned(*)[PITCH])(smu + SM_P + w * 16 * PITCH);

    // Stage Q (scale folded, tf32-rounded)
#pragma unroll
    for (int i = 0; i < 8; i++) {
        int idx = tid + i * 256;
        int row = idx >> 4, c4 = (idx & 15) << 2;
        float4 q4 = *(const float4*)(Qh + (qt * 128 + row) * 64 + c4);
        sQ[row][c4 + 0] = f2tf(q4.x * 0.125f);
        sQ[row][c4 + 1] = f2tf(q4.y * 0.125f);
        sQ[row][c4 + 2] = f2tf(q4.z * 0.125f);
        sQ[row][c4 + 3] = f2tf(q4.w * 0.125f);
    }

    float o[8][4];
#pragma unroll
    for (int nt = 0; nt < 8; nt++)
#pragma unroll
        for (int j = 0; j < 4; j++) o[nt][j] = 0.f;
    float m0 = -INFINITY, m1 = -INFINITY, l0 = 0.f, l1 = 0.f;

    const unsigned* mrow0 = g_maskbits + (qt * 128 + w * 16 + t4) * 128;
    const unsigned* mrow1 = mrow0 + 8 * 128;

    for (int kt = 0; kt < 64; kt++) {
        __syncthreads();
        // Stage K, V tiles (tf32-rounded)
#pragma unroll
        for (int i = 0; i < 4; i++) {
            int idx = tid + i * 256;
            int row = idx >> 4, c4 = (idx & 15) << 2;
            const float* kp = Kh + (kt * 64 + row) * 64 + c4;
            const float* vp = Vh + (kt * 64 + row) * 64 + c4;
            float4 k4 = *(const float4*)kp;
            float4 v4 = *(const float4*)vp;
            sK[row][c4 + 0] = f2tf(k4.x); sK[row][c4 + 1] = f2tf(k4.y);
            sK[row][c4 + 2] = f2tf(k4.z); sK[row][c4 + 3] = f2tf(k4.w);
            sV[row][c4 + 0] = f2tf(v4.x); sV[row][c4 + 1] = f2tf(v4.y);
            sV[row][c4 + 2] = f2tf(v4.z); sV[row][c4 + 3] = f2tf(v4.w);
        }
        __syncthreads();

        // S = (Q/8) @ K^T   [16 x 64 per warp]
        float s[8][4];
#pragma unroll
        for (int nt = 0; nt < 8; nt++)
#pragma unroll
            for (int j = 0; j < 4; j++) s[nt][j] = 0.f;
#pragma unroll
        for (int kc = 0; kc < 8; kc++) {
            unsigned a[4];
            a[0] = sQ[w * 16 + t4][kc * 8 + tm4];
            a[1] = sQ[w * 16 + t4 + 8][kc * 8 + tm4];
            a[2] = sQ[w * 16 + t4][kc * 8 + tm4 + 4];
            a[3] = sQ[w * 16 + t4 + 8][kc * 8 + tm4 + 4];
#pragma unroll
            for (int nt = 0; nt < 8; nt++) {
                unsigned b0 = sK[nt * 8 + t4][kc * 8 + tm4];
                unsigned b1 = sK[nt * 8 + t4][kc * 8 + tm4 + 4];
                mma8(s[nt], a, b0, b1);
            }
        }

        // Mask + online softmax. Thread owns rows (t4, t4+8), cols nt*8+tm4*2+{0,1}
        unsigned mw0a = mrow0[kt * 2], mw0b = mrow0[kt * 2 + 1];
        unsigned mw1a = mrow1[kt * 2], mw1b = mrow1[kt * 2 + 1];
        float rmax0 = -INFINITY, rmax1 = -INFINITY;
#pragma unroll
        for (int nt = 0; nt < 8; nt++) {
            int c = nt * 8 + tm4 * 2;
            unsigned w0 = (c & 32) ? mw0b : mw0a;
            unsigned w1 = (c & 32) ? mw1b : mw1a;
            int sh = c & 31;
            if ((w0 >> sh) & 1u) s[nt][0] -= 1e9f;
            if ((w0 >> (sh + 1)) & 1u) s[nt][1] -= 1e9f;
            if ((w1 >> sh) & 1u) s[nt][2] -= 1e9f;
            if ((w1 >> (sh + 1)) & 1u) s[nt][3] -= 1e9f;
            rmax0 = fmaxf(rmax0, fmaxf(s[nt][0], s[nt][1]));
            rmax1 = fmaxf(rmax1, fmaxf(s[nt][2], s[nt][3]));
        }
        rmax0 = fmaxf(rmax0, __shfl_xor_sync(0xffffffffu, rmax0, 1));
        rmax0 = fmaxf(rmax0, __shfl_xor_sync(0xffffffffu, rmax0, 2));
        rmax1 = fmaxf(rmax1, __shfl_xor_sync(0xffffffffu, rmax1, 1));
        rmax1 = fmaxf(rmax1, __shfl_xor_sync(0xffffffffu, rmax1, 2));

        float mn0 = fmaxf(m0, rmax0), mn1 = fmaxf(m1, rmax1);
        float al0 = __expf(m0 - mn0), al1 = __expf(m1 - mn1);
        m0 = mn0; m1 = mn1;

        float rs0 = 0.f, rs1 = 0.f;
#pragma unroll
        for (int nt = 0; nt < 8; nt++) {
            float p00 = __expf(s[nt][0] - mn0);
            float p01 = __expf(s[nt][1] - mn0);
            float p10 = __expf(s[nt][2] - mn1);
            float p11 = __expf(s[nt][3] - mn1);
            rs0 += p00 + p01;
            rs1 += p10 + p11;
            uint2 u0; u0.x = f2tf(p00); u0.y = f2tf(p01);
            uint2 u1; u1.x = f2tf(p10); u1.y = f2tf(p11);
            *(uint2*)&sP[t4][nt * 8 + tm4 * 2] = u0;
            *(uint2*)&sP[t4 + 8][nt * 8 + tm4 * 2] = u1;
        }
        rs0 += __shfl_xor_sync(0xffffffffu, rs0, 1);
        rs0 += __shfl_xor_sync(0xffffffffu, rs0, 2);
        rs1 += __shfl_xor_sync(0xffffffffu, rs1, 1);
        rs1 += __shfl_xor_sync(0xffffffffu, rs1, 2);
        l0 = l0 * al0 + rs0;
        l1 = l1 * al1 + rs1;
#pragma unroll
        for (int nt = 0; nt < 8; nt++) {
            o[nt][0] *= al0; o[nt][1] *= al0;
            o[nt][2] *= al1; o[nt][3] *= al1;
        }
        __syncwarp();

        // O += P @ V
        unsigned pf[8][4];
#pragma unroll
        for (int kc = 0; kc < 8; kc++) {
            pf[kc][0] = sP[t4][kc * 8 + tm4];
            pf[kc][1] = sP[t4 + 8][kc * 8 + tm4];
            pf[kc][2] = sP[t4][kc * 8 + tm4 + 4];
            pf[kc][3] = sP[t4 + 8][kc * 8 + tm4 + 4];
        }
#pragma unroll
        for (int kc = 0; kc < 8; kc++)
#pragma unroll
            for (int nt = 0; nt < 8; nt++) {
                unsigned b0 = sV[kc * 8 + tm4][nt * 8 + t4];
                unsigned b1 = sV[kc * 8 + tm4 + 4][nt * 8 + t4];
                mma8(o[nt], pf[kc], b0, b1);
            }
    }

    // Epilogue: normalize, write attn[s', h*64 + d]
    float inv0 = 1.f / l0, inv1 = 1.f / l1;
    int r0 = qt * 128 + w * 16 + t4;
    int r1 = r0 + 8;
#pragma unroll
    for (int nt = 0; nt < 8; nt++) {
        int c = h * 64 + nt * 8 + tm4 * 2;
        float2 v0 = make_float2(o[nt][0] * inv0, o[nt][1] * inv0);
        float2 v1 = make_float2(o[nt][2] * inv1, o[nt][3] * inv1);
        *(float2*)&g_attn[r0 * 512 + c] = v0;
        *(float2*)&g_attn[r1 * 512 + c] = v1;
    }
}

// ---------------------------------------------------------------------------
extern "C" void kernel_launch(void* const* d_in, const int* in_sizes, int n_in,
                              void* d_out, int out_size) {
    const float* x    = (const float*)d_in[0];
    const int*   mask = (const int*)d_in[1];
    const float* wq_w = (const float*)d_in[2];
    const float* wq_b = (const float*)d_in[3];
    const float* wk_w = (const float*)d_in[4];
    const float* wk_b = (const float*)d_in[5];
    const float* wv_w = (const float*)d_in[6];
    const float* wv_b = (const float*)d_in[7];
    const float* dw   = (const float*)d_in[8];
    const float* db   = (const float*)d_in[9];
    float* out = (float*)d_out;

    float *qp, *kp, *vp, *ap;
    cudaGetSymbolAddress((void**)&qp, g_q);
    cudaGetSymbolAddress((void**)&kp, g_k);
    cudaGetSymbolAddress((void**)&vp, g_v);
    cudaGetSymbolAddress((void**)&ap, g_attn);

    cudaFuncSetAttribute(attn_tc_kernel,
                         cudaFuncAttributeMaxDynamicSharedMemorySize,
                         ATTN_SMEM_BYTES);

    mask_pack_kernel<<<SQ * SQ / 32 / 8, 256>>>(mask);   // launch 0

    dim3 gg(512 / 64, 4096 / 128);
    gemm_tf32<<<gg, 256>>>(x, wq_w, wq_b, qp);           // 1
    gemm_tf32<<<gg, 256>>>(x, wk_w, wk_b, kp);           // 2
    gemm_tf32<<<gg, 256>>>(x, wv_w, wv_b, vp);           // 3

    dummy_kernel<<<1, 32>>>();                            // 4 (shifts ncu slot)

    attn_tc_kernel<<<dim3(32, 8), 256, ATTN_SMEM_BYTES>>>();  // 5 <- ncu -s 5

    gemm_tf32<<<gg, 256>>>(ap, dw, db, out);             // 6
}

// round 7
// speedup vs baseline: 5.2477x; 1.7460x over previous
#include <cuda_runtime.h>
#include <cuda_fp16.h>
#include <cmath>

#define SQ 4096
#define DM 512
#define HH 8
#define DKH 64

// Intermediate scratch (device globals: no allocation allowed)
__device__ __align__(16) __half g_q[SQ * DM];
__device__ __align__(16) __half g_k[SQ * DM];
__device__ __align__(16) __half g_v[SQ * DM];
__device__ float g_attn[SQ * DM];
__device__ unsigned g_maskbits[SQ * (SQ / 32)];  // 2 MB packed mask

__device__ __forceinline__ unsigned f2tf(float f) {
    unsigned u;
    asm("cvt.rna.tf32.f32 %0, %1;" : "=r"(u) : "f"(f));
    return u;
}

__device__ __forceinline__ void mma8(float* d, const unsigned* a, unsigned b0,
                                     unsigned b1) {
    asm volatile(
        "mma.sync.aligned.m16n8k8.row.col.f32.tf32.tf32.f32 "
        "{%0,%1,%2,%3},{%4,%5,%6,%7},{%8,%9},{%0,%1,%2,%3};"
        : "+f"(d[0]), "+f"(d[1]), "+f"(d[2]), "+f"(d[3])
        : "r"(a[0]), "r"(a[1]), "r"(a[2]), "r"(a[3]), "r"(b0), "r"(b1));
}

__device__ __forceinline__ void mma16(float* d, const unsigned* a, unsigned b0,
                                      unsigned b1) {
    asm volatile(
        "mma.sync.aligned.m16n8k16.row.col.f32.f16.f16.f32 "
        "{%0,%1,%2,%3},{%4,%5,%6,%7},{%8,%9},{%0,%1,%2,%3};"
        : "+f"(d[0]), "+f"(d[1]), "+f"(d[2]), "+f"(d[3])
        : "r"(a[0]), "r"(a[1]), "r"(a[2]), "r"(a[3]), "r"(b0), "r"(b1));
}

__device__ __forceinline__ void ldsm4(unsigned& r0, unsigned& r1, unsigned& r2,
                                      unsigned& r3, unsigned a) {
    asm volatile(
        "ldmatrix.sync.aligned.m8n8.x4.shared.b16 {%0,%1,%2,%3},[%4];"
        : "=r"(r0), "=r"(r1), "=r"(r2), "=r"(r3) : "r"(a));
}

__device__ __forceinline__ void ldsm4t(unsigned& r0, unsigned& r1, unsigned& r2,
                                       unsigned& r3, unsigned a) {
    asm volatile(
        "ldmatrix.sync.aligned.m8n8.x4.trans.shared.b16 {%0,%1,%2,%3},[%4];"
        : "=r"(r0), "=r"(r1), "=r"(r2), "=r"(r3) : "r"(a));
}

__device__ __forceinline__ void cpa16(unsigned dst, const void* src) {
    asm volatile("cp.async.cg.shared.global [%0],[%1],16;" ::"r"(dst),
                 "l"(src));
}
__device__ __forceinline__ void cpa_commit() {
    asm volatile("cp.async.commit_group;");
}
__device__ __forceinline__ void cpa_wait1() {
    asm volatile("cp.async.wait_group 1;");
}

// swizzled byte offset within a tile region: rows of 128 B, 16B-granule XOR
__device__ __forceinline__ unsigned swz(unsigned row, unsigned byteCol) {
    return row * 128 + ((byteCol & ~15u) ^ ((row & 7) << 4)) + (byteCol & 15);
}

// ---------------------------------------------------------------------------
// Pack int32 mask (0/1) into bits. bit index = q*4096 + k.
// ---------------------------------------------------------------------------
__global__ void mask_pack_kernel(const int* __restrict__ mask) {
    int gw = blockIdx.x * (blockDim.x >> 5) + (threadIdx.x >> 5);
    int lane = threadIdx.x & 31;
    unsigned b = __ballot_sync(0xffffffffu, mask[gw * 32 + lane] != 0);
    if (lane == 0) g_maskbits[gw] = b;
}

// Dummy: shifts attention into ncu's -s 5 -c 1 capture slot.
__global__ void dummy_kernel() {}

// ---------------------------------------------------------------------------
// tf32 tensor-core GEMM: C[4096,512] = (A[4096,512] @ B[512,512]^T + bias)*scale
// Block tile 128m x 64n, BK=32, 8 warps (4m x 2n). OutT = float or __half.
// ---------------------------------------------------------------------------
#define GPITCH 36

template <typename OutT>
__global__ void __launch_bounds__(256) gemm_tf32(const float* __restrict__ A,
                                                 const float* __restrict__ B,
                                                 const float* __restrict__ bias,
                                                 OutT* __restrict__ C,
                                                 float scale) {
    __shared__ unsigned sA[128][GPITCH];
    __shared__ unsigned sB[64][GPITCH];

    int tid = threadIdx.x;
    int w = tid >> 5, lane = tid & 31;
    int t4 = lane >> 2, tm4 = lane & 3;
    int wm = (w >> 1) * 32, wn = (w & 1) * 32;
    int m0 = blockIdx.y * 128, n0 = blockIdx.x * 64;

    int ar[4], ac4[4], br[2], bc4[2];
#pragma unroll
    for (int i = 0; i < 4; i++) {
        int idx = tid + i * 256;
        ar[i] = idx >> 3;
        ac4[i] = (idx & 7) << 2;
    }
#pragma unroll
    for (int i = 0; i < 2; i++) {
        int idx = tid + i * 256;
        br[i] = idx >> 3;
        bc4[i] = (idx & 7) << 2;
    }

    float4 aR[4], bR[2];
#pragma unroll
    for (int i = 0; i < 4; i++)
        aR[i] = *(const float4*)(A + (m0 + ar[i]) * 512 + ac4[i]);
#pragma unroll
    for (int i = 0; i < 2; i++)
        bR[i] = *(const float4*)(B + (n0 + br[i]) * 512 + bc4[i]);

    float acc[2][4][4] = {};

    for (int k0 = 0; k0 < 512; k0 += 32) {
#pragma unroll
        for (int i = 0; i < 4; i++) {
            uint4 u;
            u.x = f2tf(aR[i].x); u.y = f2tf(aR[i].y);
            u.z = f2tf(aR[i].z); u.w = f2tf(aR[i].w);
            *(uint4*)&sA[ar[i]][ac4[i]] = u;
        }
#pragma unroll
        for (int i = 0; i < 2; i++) {
            uint4 u;
            u.x = f2tf(bR[i].x); u.y = f2tf(bR[i].y);
            u.z = f2tf(bR[i].z); u.w = f2tf(bR[i].w);
            *(uint4*)&sB[br[i]][bc4[i]] = u;
        }
        __syncthreads();

        if (k0 + 32 < 512) {
#pragma unroll
            for (int i = 0; i < 4; i++)
                aR[i] = *(const float4*)(A + (m0 + ar[i]) * 512 + k0 + 32 + ac4[i]);
#pragma unroll
            for (int i = 0; i < 2; i++)
                bR[i] = *(const float4*)(B + (n0 + br[i]) * 512 + k0 + 32 + bc4[i]);
        }

#pragma unroll
        for (int kc = 0; kc < 4; kc++) {
            unsigned a[2][4];
#pragma unroll
            for (int i = 0; i < 2; i++) {
                int r = wm + i * 16;
                a[i][0] = sA[r + t4][kc * 8 + tm4];
                a[i][1] = sA[r + t4 + 8][kc * 8 + tm4];
                a[i][2] = sA[r + t4][kc * 8 + tm4 + 4];
                a[i][3] = sA[r + t4 + 8][kc * 8 + tm4 + 4];
            }
#pragma unroll
            for (int j = 0; j < 4; j++) {
                unsigned b0 = sB[wn + j * 8 + t4][kc * 8 + tm4];
                unsigned b1 = sB[wn + j * 8 + t4][kc * 8 + tm4 + 4];
                mma8(acc[0][j], a[0], b0, b1);
                mma8(acc[1][j], a[1], b0, b1);
            }
        }
        __syncthreads();
    }

#pragma unroll
    for (int i = 0; i < 2; i++) {
        int r0 = m0 + wm + i * 16 + t4;
#pragma unroll
        for (int j = 0; j < 4; j++) {
            int c = n0 + wn + j * 8 + tm4 * 2;
            float b0 = bias[c], b1 = bias[c + 1];
            float v00 = (acc[i][j][0] + b0) * scale;
            float v01 = (acc[i][j][1] + b1) * scale;
            float v10 = (acc[i][j][2] + b0) * scale;
            float v11 = (acc[i][j][3] + b1) * scale;
            if constexpr (sizeof(OutT) == 2) {
                *(__half2*)((__half*)C + r0 * 512 + c) = __floats2half2_rn(v00, v01);
                *(__half2*)((__half*)C + (r0 + 8) * 512 + c) = __floats2half2_rn(v10, v11);
            } else {
                *(float2*)((float*)C + r0 * 512 + c) = make_float2(v00, v01);
                *(float2*)((float*)C + (r0 + 8) * 512 + c) = make_float2(v10, v11);
            }
        }
    }
}

// ---------------------------------------------------------------------------
// fp16 tensor-core flash attention (m16n8k16, fp32 accumulate).
// Block = 128 q-rows x 1 head. 8 warps x 16 q-rows. BK=64, cp.async 2-stage.
// smem layout (bytes): Q[0,16K) K[16K,32K) x2stg V[32K,48K) x2stg P[48K,64K)
// ---------------------------------------------------------------------------
#define SMQ 0
#define SMK 16384
#define SMV 32768
#define SMP 49152
#define ASMEM 65536

__global__ void __launch_bounds__(256, 2) attn_fp16() {
    extern __shared__ char sm[];
    unsigned sb = (unsigned)__cvta_generic_to_shared(sm);
    int tid = threadIdx.x;
    int w = tid >> 5, lane = tid & 31;
    int t4 = lane >> 2, tm4 = lane & 3;
    int qt = blockIdx.x, h = blockIdx.y;

    const __half* Qh = g_q + h * (SQ * DKH);
    const __half* Kh = g_k + h * (SQ * DKH);
    const __half* Vh = g_v + h * (SQ * DKH);

    int srow = tid >> 3, scd = tid & 7;  // staging row/chunk (per 256-thread pass)

    // Stage Q (16KB = 1024 chunks) + K/V tile 0 (512 chunks each)
#pragma unroll
    for (int i = 0; i < 4; i++) {
        int idx = tid + i * 256;
        int row = idx >> 3, cd = idx & 7;
        cpa16(sb + SMQ + swz(row, cd * 16), Qh + (qt * 128 + row) * 64 + cd * 8);
    }
#pragma unroll
    for (int i = 0; i < 2; i++) {
        int row = srow + i * 32;
        cpa16(sb + SMK + swz(row, scd * 16), Kh + row * 64 + scd * 8);
        cpa16(sb + SMV + swz(row, scd * 16), Vh + row * 64 + scd * 8);
    }
    cpa_commit();

    float o[8][4];
#pragma unroll
    for (int nt = 0; nt < 8; nt++)
#pragma unroll
        for (int j = 0; j < 4; j++) o[nt][j] = 0.f;
    float m0 = -INFINITY, m1 = -INFINITY, l0 = 0.f, l1 = 0.f;

    const unsigned* mrow0 = g_maskbits + (qt * 128 + w * 16 + t4) * 128;
    const unsigned* mrow1 = mrow0 + 8 * 128;

    unsigned qrow = w * 16 + (lane & 15);
    unsigned lrow = lane & 15;
    unsigned hi16 = ((lane >> 4) & 1) * 16;
    unsigned pb = sb + SMP + w * 2048;

    for (int kt = 0; kt < 64; kt++) {
        __syncthreads();  // all warps done computing on buf[(kt+1)&1] (iter kt-1)
        if (kt + 1 < 64) {
            int buf = (kt + 1) & 1;
#pragma unroll
            for (int i = 0; i < 2; i++) {
                int row = srow + i * 32;
                int gr = (kt + 1) * 64 + row;
                cpa16(sb + SMK + buf * 8192 + swz(row, scd * 16), Kh + gr * 64 + scd * 8);
                cpa16(sb + SMV + buf * 8192 + swz(row, scd * 16), Vh + gr * 64 + scd * 8);
            }
        }
        cpa_commit();
        cpa_wait1();  // stage kt resident
        __syncthreads();

        // mask words early (L2 latency hides under S-mma)
        unsigned mw0a = mrow0[kt * 2], mw0b = mrow0[kt * 2 + 1];
        unsigned mw1a = mrow1[kt * 2], mw1b = mrow1[kt * 2 + 1];

        unsigned kbase = sb + SMK + (kt & 1) * 8192;
        unsigned vbase = sb + SMV + (kt & 1) * 8192;

        // Q fragments (scale 1/8 pre-folded by gemm)
        unsigned qf[4][4];
#pragma unroll
        for (int kc = 0; kc < 4; kc++)
            ldsm4(qf[kc][0], qf[kc][1], qf[kc][2], qf[kc][3],
                  sb + SMQ + swz(qrow, kc * 32 + hi16));

        // S = Q @ K^T   [16 x 64 per warp]
        float s[8][4];
#pragma unroll
        for (int nt = 0; nt < 8; nt++)
#pragma unroll
            for (int j = 0; j < 4; j++) s[nt][j] = 0.f;
#pragma unroll
        for (int kc = 0; kc < 4; kc++)
#pragma unroll
            for (int ng = 0; ng < 4; ng++) {
                unsigned b0, b1, b2, b3;
                ldsm4(b0, b1, b2, b3,
                      kbase + swz(ng * 16 + lrow, kc * 32 + hi16));
                mma16(s[2 * ng], qf[kc], b0, b2);
                mma16(s[2 * ng + 1], qf[kc], b1, b3);
            }

        // Mask + online softmax. Rows (t4, t4+8), cols nt*8+tm4*2+{0,1}
        float rmax0 = -INFINITY, rmax1 = -INFINITY;
#pragma unroll
        for (int nt = 0; nt < 8; nt++) {
            int c = nt * 8 + tm4 * 2;
            unsigned w0 = (c & 32) ? mw0b : mw0a;
            unsigned w1 = (c & 32) ? mw1b : mw1a;
            int sh = c & 31;
            if ((w0 >> sh) & 1u) s[nt][0] -= 1e9f;
            if ((w0 >> (sh + 1)) & 1u) s[nt][1] -= 1e9f;
            if ((w1 >> sh) & 1u) s[nt][2] -= 1e9f;
            if ((w1 >> (sh + 1)) & 1u) s[nt][3] -= 1e9f;
            rmax0 = fmaxf(rmax0, fmaxf(s[nt][0], s[nt][1]));
            rmax1 = fmaxf(rmax1, fmaxf(s[nt][2], s[nt][3]));
        }
        rmax0 = fmaxf(rmax0, __shfl_xor_sync(0xffffffffu, rmax0, 1));
        rmax0 = fmaxf(rmax0, __shfl_xor_sync(0xffffffffu, rmax0, 2));
        rmax1 = fmaxf(rmax1, __shfl_xor_sync(0xffffffffu, rmax1, 1));
        rmax1 = fmaxf(rmax1, __shfl_xor_sync(0xffffffffu, rmax1, 2));

        float mn0 = fmaxf(m0, rmax0), mn1 = fmaxf(m1, rmax1);
        float al0 = __expf(m0 - mn0), al1 = __expf(m1 - mn1);
        m0 = mn0; m1 = mn1;

        float rs0 = 0.f, rs1 = 0.f;
#pragma unroll
        for (int nt = 0; nt < 8; nt++) {
            float p00 = __expf(s[nt][0] - mn0);
            float p01 = __expf(s[nt][1] - mn0);
            float p10 = __expf(s[nt][2] - mn1);
            float p11 = __expf(s[nt][3] - mn1);
            rs0 += p00 + p01;
            rs1 += p10 + p11;
            unsigned bc = nt * 16 + tm4 * 4;
            *(__half2*)(sm + SMP + w * 2048 + swz(t4, bc)) =
                __floats2half2_rn(p00, p01);
            *(__half2*)(sm + SMP + w * 2048 + swz(t4 + 8, bc)) =
                __floats2half2_rn(p10, p11);
        }
        rs0 += __shfl_xor_sync(0xffffffffu, rs0, 1);
        rs0 += __shfl_xor_sync(0xffffffffu, rs0, 2);
        rs1 += __shfl_xor_sync(0xffffffffu, rs1, 1);
        rs1 += __shfl_xor_sync(0xffffffffu, rs1, 2);
        l0 = l0 * al0 + rs0;
        l1 = l1 * al1 + rs1;
#pragma unroll
        for (int nt = 0; nt < 8; nt++) {
            o[nt][0] *= al0; o[nt][1] *= al0;
            o[nt][2] *= al1; o[nt][3] *= al1;
        }
        __syncwarp();

        // P fragments (own warp's 16 rows)
        unsigned pf[4][4];
#pragma unroll
        for (int kc = 0; kc < 4; kc++)
            ldsm4(pf[kc][0], pf[kc][1], pf[kc][2], pf[kc][3],
                  pb + swz(lrow, kc * 32 + hi16));

        // O += P @ V   (V via ldmatrix.trans: frag (k=key, n=d))
#pragma unroll
        for (int kc = 0; kc < 4; kc++)
#pragma unroll
            for (int ng = 0; ng < 4; ng++) {
                unsigned v0, v1, v2, v3;
                ldsm4t(v0, v1, v2, v3,
                       vbase + swz(kc * 16 + lrow, ng * 32 + hi16));
                mma16(o[2 * ng], pf[kc], v0, v1);
                mma16(o[2 * ng + 1], pf[kc], v2, v3);
            }
    }

    // Epilogue: normalize, write attn[s', h*64 + d]
    float inv0 = 1.f / l0, inv1 = 1.f / l1;
    int r0 = qt * 128 + w * 16 + t4;
    int r1 = r0 + 8;
#pragma unroll
    for (int nt = 0; nt < 8; nt++) {
        int c = h * 64 + nt * 8 + tm4 * 2;
        *(float2*)&g_attn[r0 * 512 + c] =
            make_float2(o[nt][0] * inv0, o[nt][1] * inv0);
        *(float2*)&g_attn[r1 * 512 + c] =
            make_float2(o[nt][2] * inv1, o[nt][3] * inv1);
    }
}

// ---------------------------------------------------------------------------
extern "C" void kernel_launch(void* const* d_in, const int* in_sizes, int n_in,
                              void* d_out, int out_size) {
    const float* x    = (const float*)d_in[0];
    const int*   mask = (const int*)d_in[1];
    const float* wq_w = (const float*)d_in[2];
    const float* wq_b = (const float*)d_in[3];
    const float* wk_w = (const float*)d_in[4];
    const float* wk_b = (const float*)d_in[5];
    const float* wv_w = (const float*)d_in[6];
    const float* wv_b = (const float*)d_in[7];
    const float* dw   = (const float*)d_in[8];
    const float* db   = (const float*)d_in[9];
    float* out = (float*)d_out;

    __half *qp, *kp, *vp;
    float* ap;
    cudaGetSymbolAddress((void**)&qp, g_q);
    cudaGetSymbolAddress((void**)&kp, g_k);
    cudaGetSymbolAddress((void**)&vp, g_v);
    cudaGetSymbolAddress((void**)&ap, g_attn);

    cudaFuncSetAttribute(attn_fp16,
                         cudaFuncAttributeMaxDynamicSharedMemorySize, ASMEM);

    mask_pack_kernel<<<SQ * SQ / 32 / 8, 256>>>(mask);   // launch 0

    dim3 gg(512 / 64, 4096 / 128);
    gemm_tf32<__half><<<gg, 256>>>(x, wq_w, wq_b, qp, 0.125f);  // 1
    gemm_tf32<__half><<<gg, 256>>>(x, wk_w, wk_b, kp, 1.0f);    // 2
    gemm_tf32<__half><<<gg, 256>>>(x, wv_w, wv_b, vp, 1.0f);    // 3

    dummy_kernel<<<1, 32>>>();                                   // 4

    attn_fp16<<<dim3(32, 8), 256, ASMEM>>>();                    // 5 <- ncu -s 5

    gemm_tf32<float><<<gg, 256>>>(ap, dw, db, out, 1.0f);        // 6
}

// round 8
// speedup vs baseline: 7.2323x; 1.3782x over previous
#include <cuda_runtime.h>
#include <cuda_fp16.h>
#include <cmath>

#define SQ 4096
#define DM 512
#define HH 8
#define DKH 64

// Device-global scratch (no allocation allowed)
__device__ __align__(16) __half g_q[SQ * DM];
__device__ __align__(16) __half g_k[SQ * DM];
__device__ __align__(16) __half g_v[SQ * DM];
__device__ __align__(16) __half g_attnh[SQ * DM];
__device__ __align__(16) __half g_xh[SQ * DM];
__device__ __align__(16) __half g_wqh[DM * DM];
__device__ __align__(16) __half g_wkh[DM * DM];
__device__ __align__(16) __half g_wvh[DM * DM];
__device__ __align__(16) __half g_wdh[DM * DM];
__device__ unsigned g_maskbits[SQ * (SQ / 32)];  // 2 MB packed mask

__device__ __forceinline__ void mma16(float* d, const unsigned* a, unsigned b0,
                                      unsigned b1) {
    asm volatile(
        "mma.sync.aligned.m16n8k16.row.col.f32.f16.f16.f32 "
        "{%0,%1,%2,%3},{%4,%5,%6,%7},{%8,%9},{%0,%1,%2,%3};"
        : "+f"(d[0]), "+f"(d[1]), "+f"(d[2]), "+f"(d[3])
        : "r"(a[0]), "r"(a[1]), "r"(a[2]), "r"(a[3]), "r"(b0), "r"(b1));
}

__device__ __forceinline__ void ldsm4(unsigned& r0, unsigned& r1, unsigned& r2,
                                      unsigned& r3, unsigned a) {
    asm volatile(
        "ldmatrix.sync.aligned.m8n8.x4.shared.b16 {%0,%1,%2,%3},[%4];"
        : "=r"(r0), "=r"(r1), "=r"(r2), "=r"(r3) : "r"(a));
}

__device__ __forceinline__ void ldsm4t(unsigned& r0, unsigned& r1, unsigned& r2,
                                       unsigned& r3, unsigned a) {
    asm volatile(
        "ldmatrix.sync.aligned.m8n8.x4.trans.shared.b16 {%0,%1,%2,%3},[%4];"
        : "=r"(r0), "=r"(r1), "=r"(r2), "=r"(r3) : "r"(a));
}

__device__ __forceinline__ void cpa16(unsigned dst, const void* src) {
    asm volatile("cp.async.cg.shared.global [%0],[%1],16;" ::"r"(dst),
                 "l"(src));
}
__device__ __forceinline__ void cpa_commit() {
    asm volatile("cp.async.commit_group;");
}
__device__ __forceinline__ void cpa_wait0() {
    asm volatile("cp.async.wait_group 0;");
}

// swizzled byte offset within a tile region: rows of 128 B, 16B-granule XOR
__device__ __forceinline__ unsigned swz(unsigned row, unsigned byteCol) {
    return row * 128 + ((byteCol & ~15u) ^ ((row & 7) << 4)) + (byteCol & 15);
}

__device__ __forceinline__ unsigned h2u(float a, float b) {
    __half2 h = __floats2half2_rn(a, b);
    return *(unsigned*)&h;
}

// ---------------------------------------------------------------------------
// Pack int32 mask into bits. bit index = q*4096 + k.
// ---------------------------------------------------------------------------
__global__ void mask_pack_kernel(const int* __restrict__ mask) {
    int gw = blockIdx.x * (blockDim.x >> 5) + (threadIdx.x >> 5);
    int lane = threadIdx.x & 31;
    unsigned b = __ballot_sync(0xffffffffu, mask[gw * 32 + lane] != 0);
    if (lane == 0) g_maskbits[gw] = b;
}

// ---------------------------------------------------------------------------
// Convert x and the 4 weight matrices to fp16 (one pass, float4-granular).
// quads: [0,524288) = x ; then 4 x 65536 per weight.
// ---------------------------------------------------------------------------
__global__ void __launch_bounds__(256) cvt_kernel(const float* __restrict__ x,
                                                  const float* __restrict__ wq,
                                                  const float* __restrict__ wk,
                                                  const float* __restrict__ wv,
                                                  const float* __restrict__ wd) {
    unsigned q = blockIdx.x * 256 + threadIdx.x;
    const float* src;
    __half* dst;
    unsigned off;
    if (q < 524288u) {
        src = x; dst = g_xh; off = q;
    } else {
        unsigned r = (q - 524288u) >> 16;
        off = (q - 524288u) & 65535u;
        src = (r == 0) ? wq : (r == 1) ? wk : (r == 2) ? wv : wd;
        dst = (r == 0) ? g_wqh : (r == 1) ? g_wkh : (r == 2) ? g_wvh : g_wdh;
    }
    float4 v = ((const float4*)src)[off];
    ((__half2*)dst)[off * 2] = __floats2half2_rn(v.x, v.y);
    ((__half2*)dst)[off * 2 + 1] = __floats2half2_rn(v.z, v.w);
}

// ---------------------------------------------------------------------------
// fp16 tensor-core GEMM: C[4096,512] = (A @ B^T + bias) * scale
// A,B fp16 row-major. Block 128m x 64n, BK=64, cp.async double-buffered.
// 8 warps (4m x 2n), warp tile 32x32. OutT = __half or float.
// smem: A 16KB x2 @0, B 8KB x2 @32768.
// ---------------------------------------------------------------------------
template <typename OutT>
__global__ void __launch_bounds__(256, 2) gemm_h(const __half* __restrict__ A,
                                                 const __half* __restrict__ B,
                                                 const float* __restrict__ bias,
                                                 OutT* __restrict__ C,
                                                 float scale) {
    __shared__ __align__(128) char gsm[49152];
    unsigned sb = (unsigned)__cvta_generic_to_shared(gsm);

    int tid = threadIdx.x;
    int w = tid >> 5, lane = tid & 31;
    int t4 = lane >> 2, tm4 = lane & 3;
    unsigned lrow = lane & 15;
    unsigned hi16 = ((lane >> 4) & 1) * 16;
    int wm = (w >> 1) * 32, wn = (w & 1) * 32;
    int m0 = blockIdx.y * 128, n0 = blockIdx.x * 64;

    int srow = tid >> 3, scd = tid & 7;

    // Prologue: stage tile 0
#pragma unroll
    for (int i = 0; i < 4; i++) {
        int idx = tid + i * 256;
        int row = idx >> 3, cd = idx & 7;
        cpa16(sb + swz(row, cd * 16), A + (m0 + row) * 512 + cd * 8);
    }
#pragma unroll
    for (int i = 0; i < 2; i++) {
        int row = srow + i * 32;
        cpa16(sb + 32768 + swz(row, scd * 16), B + (n0 + row) * 512 + scd * 8);
    }
    cpa_commit();

    float acc[2][4][4] = {};

    for (int it = 0; it < 8; it++) {
        cpa_wait0();
        __syncthreads();
        if (it + 1 < 8) {
            int buf = (it + 1) & 1;
            int k0 = (it + 1) * 64;
#pragma unroll
            for (int i = 0; i < 4; i++) {
                int idx = tid + i * 256;
                int row = idx >> 3, cd = idx & 7;
                cpa16(sb + buf * 16384 + swz(row, cd * 16),
                      A + (m0 + row) * 512 + k0 + cd * 8);
            }
#pragma unroll
            for (int i = 0; i < 2; i++) {
                int row = srow + i * 32;
                cpa16(sb + 32768 + buf * 8192 + swz(row, scd * 16),
                      B + (n0 + row) * 512 + k0 + scd * 8);
            }
            cpa_commit();
        }

        unsigned abase = sb + (it & 1) * 16384;
        unsigned bbase = sb + 32768 + (it & 1) * 8192;
#pragma unroll
        for (int kc = 0; kc < 4; kc++) {
            unsigned af[2][4];
#pragma unroll
            for (int g = 0; g < 2; g++)
                ldsm4(af[g][0], af[g][1], af[g][2], af[g][3],
                      abase + swz(wm + g * 16 + lrow, kc * 32 + hi16));
#pragma unroll
            for (int ng = 0; ng < 2; ng++) {
                unsigned b0, b1, b2, b3;
                ldsm4(b0, b1, b2, b3,
                      bbase + swz(wn + ng * 16 + lrow, kc * 32 + hi16));
                mma16(acc[0][2 * ng], af[0], b0, b2);
                mma16(acc[0][2 * ng + 1], af[0], b1, b3);
                mma16(acc[1][2 * ng], af[1], b0, b2);
                mma16(acc[1][2 * ng + 1], af[1], b1, b3);
            }
        }
    }

#pragma unroll
    for (int g = 0; g < 2; g++) {
        int r0 = m0 + wm + g * 16 + t4;
#pragma unroll
        for (int nt = 0; nt < 4; nt++) {
            int c = n0 + wn + nt * 8 + tm4 * 2;
            float b0 = bias[c], b1 = bias[c + 1];
            float v00 = (acc[g][nt][0] + b0) * scale;
            float v01 = (acc[g][nt][1] + b1) * scale;
            float v10 = (acc[g][nt][2] + b0) * scale;
            float v11 = (acc[g][nt][3] + b1) * scale;
            if constexpr (sizeof(OutT) == 2) {
                *(__half2*)((__half*)C + r0 * 512 + c) = __floats2half2_rn(v00, v01);
                *(__half2*)((__half*)C + (r0 + 8) * 512 + c) = __floats2half2_rn(v10, v11);
            } else {
                *(float2*)((float*)C + r0 * 512 + c) = make_float2(v00, v01);
                *(float2*)((float*)C + (r0 + 8) * 512 + c) = make_float2(v10, v11);
            }
        }
    }
}

// ---------------------------------------------------------------------------
// fp16 flash attention (m16n8k16, fp32 accumulate), log2-domain softmax.
// Block = 128 q-rows x 1 head. 8 warps x 16 q-rows. BK=64, 2-stage cp.async.
// smem: Q[0,16K) K[16K,32K) x2stg V[32K,48K) x2stg. P lives in registers.
// Q pre-scaled by 0.125*log2e in the projection gemm.
// ---------------------------------------------------------------------------
#define SMK 16384
#define SMV 32768
#define ASMEM 49152

__global__ void __launch_bounds__(256, 2) attn_fp16() {
    extern __shared__ char sm[];
    unsigned sb = (unsigned)__cvta_generic_to_shared(sm);
    int tid = threadIdx.x;
    int w = tid >> 5, lane = tid & 31;
    int t4 = lane >> 2, tm4 = lane & 3;
    int qt = blockIdx.x, h = blockIdx.y;

    const __half* Qh = g_q + h * (SQ * DKH);
    const __half* Kh = g_k + h * (SQ * DKH);
    const __half* Vh = g_v + h * (SQ * DKH);

    int srow = tid >> 3, scd = tid & 7;

    // Prologue: stage Q + K0/V0
#pragma unroll
    for (int i = 0; i < 4; i++) {
        int idx = tid + i * 256;
        int row = idx >> 3, cd = idx & 7;
        cpa16(sb + swz(row, cd * 16), Qh + (qt * 128 + row) * 64 + cd * 8);
    }
#pragma unroll
    for (int i = 0; i < 2; i++) {
        int row = srow + i * 32;
        cpa16(sb + SMK + swz(row, scd * 16), Kh + row * 64 + scd * 8);
        cpa16(sb + SMV + swz(row, scd * 16), Vh + row * 64 + scd * 8);
    }
    cpa_commit();

    unsigned qrow = w * 16 + (lane & 15);
    unsigned lrow = lane & 15;
    unsigned hi16 = ((lane >> 4) & 1) * 16;

    cpa_wait0();
    __syncthreads();

    // Q fragments: loop-invariant, register-resident
    unsigned qf[4][4];
#pragma unroll
    for (int kc = 0; kc < 4; kc++)
        ldsm4(qf[kc][0], qf[kc][1], qf[kc][2], qf[kc][3],
              sb + swz(qrow, kc * 32 + hi16));

    float o[8][4];
#pragma unroll
    for (int nt = 0; nt < 8; nt++)
#pragma unroll
        for (int j = 0; j < 4; j++) o[nt][j] = 0.f;
    float m0 = -INFINITY, m1 = -INFINITY, l0 = 0.f, l1 = 0.f;

    const unsigned* mrow0 = g_maskbits + (qt * 128 + w * 16 + t4) * 128;
    const unsigned* mrow1 = mrow0 + 8 * 128;

    for (int kt = 0; kt < 64; kt++) {
        if (kt) {
            cpa_wait0();
            __syncthreads();
        }
        if (kt + 1 < 64) {
            int buf = (kt + 1) & 1;
#pragma unroll
            for (int i = 0; i < 2; i++) {
                int row = srow + i * 32;
                int gr = (kt + 1) * 64 + row;
                cpa16(sb + SMK + buf * 8192 + swz(row, scd * 16),
                      Kh + gr * 64 + scd * 8);
                cpa16(sb + SMV + buf * 8192 + swz(row, scd * 16),
                      Vh + gr * 64 + scd * 8);
            }
            cpa_commit();
        }

        // mask words early (L2 latency hides under S-mma)
        unsigned mw0a = mrow0[kt * 2], mw0b = mrow0[kt * 2 + 1];
        unsigned mw1a = mrow1[kt * 2], mw1b = mrow1[kt * 2 + 1];

        unsigned kbase = sb + SMK + (kt & 1) * 8192;
        unsigned vbase = sb + SMV + (kt & 1) * 8192;

        // S = Q' @ K^T  (already in log2 units)
        float s[8][4];
#pragma unroll
        for (int nt = 0; nt < 8; nt++)
#pragma unroll
            for (int j = 0; j < 4; j++) s[nt][j] = 0.f;
#pragma unroll
        for (int kc = 0; kc < 4; kc++)
#pragma unroll
            for (int ng = 0; ng < 4; ng++) {
                unsigned b0, b1, b2, b3;
                ldsm4(b0, b1, b2, b3,
                      kbase + swz(ng * 16 + lrow, kc * 32 + hi16));
                mma16(s[2 * ng], qf[kc], b0, b2);
                mma16(s[2 * ng + 1], qf[kc], b1, b3);
            }

        // Mask + online softmax (base-2)
        float rmax0 = -INFINITY, rmax1 = -INFINITY;
#pragma unroll
        for (int nt = 0; nt < 8; nt++) {
            int c = nt * 8 + tm4 * 2;
            unsigned w0 = (c & 32) ? mw0b : mw0a;
            unsigned w1 = (c & 32) ? mw1b : mw1a;
            int sh = c & 31;
            if ((w0 >> sh) & 1u) s[nt][0] -= 1e9f;
            if ((w0 >> (sh + 1)) & 1u) s[nt][1] -= 1e9f;
            if ((w1 >> sh) & 1u) s[nt][2] -= 1e9f;
            if ((w1 >> (sh + 1)) & 1u) s[nt][3] -= 1e9f;
            rmax0 = fmaxf(rmax0, fmaxf(s[nt][0], s[nt][1]));
            rmax1 = fmaxf(rmax1, fmaxf(s[nt][2], s[nt][3]));
        }
        rmax0 = fmaxf(rmax0, __shfl_xor_sync(0xffffffffu, rmax0, 1));
        rmax0 = fmaxf(rmax0, __shfl_xor_sync(0xffffffffu, rmax0, 2));
        rmax1 = fmaxf(rmax1, __shfl_xor_sync(0xffffffffu, rmax1, 1));
        rmax1 = fmaxf(rmax1, __shfl_xor_sync(0xffffffffu, rmax1, 2));

        float mn0 = fmaxf(m0, rmax0), mn1 = fmaxf(m1, rmax1);
        float al0 = exp2f(m0 - mn0), al1 = exp2f(m1 - mn1);
        m0 = mn0; m1 = mn1;

        // P packed straight into A-fragment registers (no smem round trip)
        unsigned pf[4][4];
        float rs0 = 0.f, rs1 = 0.f;
#pragma unroll
        for (int nt = 0; nt < 8; nt++) {
            float p00 = exp2f(s[nt][0] - mn0);
            float p01 = exp2f(s[nt][1] - mn0);
            float p10 = exp2f(s[nt][2] - mn1);
            float p11 = exp2f(s[nt][3] - mn1);
            rs0 += p00 + p01;
            rs1 += p10 + p11;
            int kc = nt >> 1, base = (nt & 1) * 2;
            pf[kc][base] = h2u(p00, p01);
            pf[kc][base + 1] = h2u(p10, p11);
        }
        rs0 += __shfl_xor_sync(0xffffffffu, rs0, 1);
        rs0 += __shfl_xor_sync(0xffffffffu, rs0, 2);
        rs1 += __shfl_xor_sync(0xffffffffu, rs1, 1);
        rs1 += __shfl_xor_sync(0xffffffffu, rs1, 2);
        l0 = l0 * al0 + rs0;
        l1 = l1 * al1 + rs1;
#pragma unroll
        for (int nt = 0; nt < 8; nt++) {
            o[nt][0] *= al0; o[nt][1] *= al0;
            o[nt][2] *= al1; o[nt][3] *= al1;
        }

        // O += P @ V   (V via ldmatrix.trans)
#pragma unroll
        for (int kc = 0; kc < 4; kc++)
#pragma unroll
            for (int ng = 0; ng < 4; ng++) {
                unsigned v0, v1, v2, v3;
                ldsm4t(v0, v1, v2, v3,
                       vbase + swz(kc * 16 + lrow, ng * 32 + hi16));
                mma16(o[2 * ng], pf[kc], v0, v1);
                mma16(o[2 * ng + 1], pf[kc], v2, v3);
            }
    }

    // Epilogue: normalize, write fp16 attn[s', h*64 + d]
    float inv0 = 1.f / l0, inv1 = 1.f / l1;
    int r0 = qt * 128 + w * 16 + t4;
    int r1 = r0 + 8;
#pragma unroll
    for (int nt = 0; nt < 8; nt++) {
        int c = h * 64 + nt * 8 + tm4 * 2;
        *(__half2*)&g_attnh[r0 * 512 + c] =
            __floats2half2_rn(o[nt][0] * inv0, o[nt][1] * inv0);
        *(__half2*)&g_attnh[r1 * 512 + c] =
            __floats2half2_rn(o[nt][2] * inv1, o[nt][3] * inv1);
    }
}

// ---------------------------------------------------------------------------
extern "C" void kernel_launch(void* const* d_in, const int* in_sizes, int n_in,
                              void* d_out, int out_size) {
    const float* x    = (const float*)d_in[0];
    const int*   mask = (const int*)d_in[1];
    const float* wq_w = (const float*)d_in[2];
    const float* wq_b = (const float*)d_in[3];
    const float* wk_w = (const float*)d_in[4];
    const float* wk_b = (const float*)d_in[5];
    const float* wv_w = (const float*)d_in[6];
    const float* wv_b = (const float*)d_in[7];
    const float* dw   = (const float*)d_in[8];
    const float* db   = (const float*)d_in[9];
    float* out = (float*)d_out;

    __half *qp, *kp, *vp, *xp, *ah, *wqh, *wkh, *wvh, *wdh;
    cudaGetSymbolAddress((void**)&qp, g_q);
    cudaGetSymbolAddress((void**)&kp, g_k);
    cudaGetSymbolAddress((void**)&vp, g_v);
    cudaGetSymbolAddress((void**)&xp, g_xh);
    cudaGetSymbolAddress((void**)&ah, g_attnh);
    cudaGetSymbolAddress((void**)&wqh, g_wqh);
    cudaGetSymbolAddress((void**)&wkh, g_wkh);
    cudaGetSymbolAddress((void**)&wvh, g_wvh);
    cudaGetSymbolAddress((void**)&wdh, g_wdh);

    cudaFuncSetAttribute(attn_fp16,
                         cudaFuncAttributeMaxDynamicSharedMemorySize, ASMEM);

    const float QSCALE = 0.125f * 1.44269504f;  // fold 1/sqrt(dk) and log2e

    mask_pack_kernel<<<SQ * SQ / 32 / 8, 256>>>(mask);          // launch 1
    cvt_kernel<<<3072, 256>>>(x, wq_w, wk_w, wv_w, dw);         // launch 2

    dim3 gg(512 / 64, 4096 / 128);
    gemm_h<__half><<<gg, 256>>>(xp, wqh, wq_b, qp, QSCALE);     // launch 3
    gemm_h<__half><<<gg, 256>>>(xp, wkh, wk_b, kp, 1.0f);       // launch 4
    gemm_h<__half><<<gg, 256>>>(xp, wvh, wv_b, vp, 1.0f);       // launch 5

    attn_fp16<<<dim3(32, 8), 256, ASMEM>>>();                   // launch 6 <- ncu -s 5

    gemm_h<float><<<gg, 256>>>(ah, wdh, db, out, 1.0f);         // launch 7
}

// round 9
// speedup vs baseline: 7.4243x; 1.0265x over previous
#include <cuda_runtime.h>
#include <cuda_fp16.h>
#include <cmath>

#define SQ 4096
#define DM 512
#define HH 8
#define DKH 64

// Device-global scratch (no allocation allowed)
__device__ __align__(16) __half g_q[SQ * DM];
__device__ __align__(16) __half g_k[SQ * DM];
__device__ __align__(16) __half g_v[SQ * DM];
__device__ __align__(16) __half g_attnh[SQ * DM];
__device__ __align__(16) __half g_xh[SQ * DM];
__device__ __align__(16) __half g_wqh[DM * DM];
__device__ __align__(16) __half g_wkh[DM * DM];
__device__ __align__(16) __half g_wvh[DM * DM];
__device__ __align__(16) __half g_wdh[DM * DM];
__device__ unsigned g_maskbits[SQ * (SQ / 32)];  // 2 MB packed mask

__device__ __forceinline__ void mma16(float* d, const unsigned* a, unsigned b0,
                                      unsigned b1) {
    asm volatile(
        "mma.sync.aligned.m16n8k16.row.col.f32.f16.f16.f32 "
        "{%0,%1,%2,%3},{%4,%5,%6,%7},{%8,%9},{%0,%1,%2,%3};"
        : "+f"(d[0]), "+f"(d[1]), "+f"(d[2]), "+f"(d[3])
        : "r"(a[0]), "r"(a[1]), "r"(a[2]), "r"(a[3]), "r"(b0), "r"(b1));
}

__device__ __forceinline__ void ldsm4(unsigned& r0, unsigned& r1, unsigned& r2,
                                      unsigned& r3, unsigned a) {
    asm volatile(
        "ldmatrix.sync.aligned.m8n8.x4.shared.b16 {%0,%1,%2,%3},[%4];"
        : "=r"(r0), "=r"(r1), "=r"(r2), "=r"(r3) : "r"(a));
}

__device__ __forceinline__ void ldsm4t(unsigned& r0, unsigned& r1, unsigned& r2,
                                       unsigned& r3, unsigned a) {
    asm volatile(
        "ldmatrix.sync.aligned.m8n8.x4.trans.shared.b16 {%0,%1,%2,%3},[%4];"
        : "=r"(r0), "=r"(r1), "=r"(r2), "=r"(r3) : "r"(a));
}

__device__ __forceinline__ void cpa16(unsigned dst, const void* src) {
    asm volatile("cp.async.cg.shared.global [%0],[%1],16;" ::"r"(dst),
                 "l"(src));
}
__device__ __forceinline__ void cpa_commit() {
    asm volatile("cp.async.commit_group;");
}
__device__ __forceinline__ void cpa_wait0() {
    asm volatile("cp.async.wait_group 0;");
}
__device__ __forceinline__ void cpa_wait1() {
    asm volatile("cp.async.wait_group 1;");
}
__device__ __forceinline__ void cpa_wait2() {
    asm volatile("cp.async.wait_group 2;");
}

// pack two f32 -> f16x2 (lo,hi), then 2^x elementwise on MUFU (one instr)
__device__ __forceinline__ unsigned ex2x2(float lo, float hi) {
    unsigned u;
    asm("{.reg .b32 t;\n\t"
        "cvt.rn.f16x2.f32 t, %2, %1;\n\t"
        "ex2.approx.f16x2 %0, t;}"
        : "=r"(u) : "f"(lo), "f"(hi));
    return u;
}

// swizzled byte offset within a tile region: rows of 128 B, 16B-granule XOR
__device__ __forceinline__ unsigned swz(unsigned row, unsigned byteCol) {
    return row * 128 + ((byteCol & ~15u) ^ ((row & 7) << 4)) + (byteCol & 15);
}

// ---------------------------------------------------------------------------
// Pack int32 mask into bits. bit index = q*4096 + k.
// ---------------------------------------------------------------------------
__global__ void mask_pack_kernel(const int* __restrict__ mask) {
    int gw = blockIdx.x * (blockDim.x >> 5) + (threadIdx.x >> 5);
    int lane = threadIdx.x & 31;
    unsigned b = __ballot_sync(0xffffffffu, mask[gw * 32 + lane] != 0);
    if (lane == 0) g_maskbits[gw] = b;
}

// ---------------------------------------------------------------------------
// Convert x and the 4 weight matrices to fp16 (one pass, float4-granular).
// ---------------------------------------------------------------------------
__global__ void __launch_bounds__(256) cvt_kernel(const float* __restrict__ x,
                                                  const float* __restrict__ wq,
                                                  const float* __restrict__ wk,
                                                  const float* __restrict__ wv,
                                                  const float* __restrict__ wd) {
    unsigned q = blockIdx.x * 256 + threadIdx.x;
    const float* src;
    __half* dst;
    unsigned off;
    if (q < 524288u) {
        src = x; dst = g_xh; off = q;
    } else {
        unsigned r = (q - 524288u) >> 16;
        off = (q - 524288u) & 65535u;
        src = (r == 0) ? wq : (r == 1) ? wk : (r == 2) ? wv : wd;
        dst = (r == 0) ? g_wqh : (r == 1) ? g_wkh : (r == 2) ? g_wvh : g_wdh;
    }
    float4 v = ((const float4*)src)[off];
    ((__half2*)dst)[off * 2] = __floats2half2_rn(v.x, v.y);
    ((__half2*)dst)[off * 2 + 1] = __floats2half2_rn(v.z, v.w);
}

// ---------------------------------------------------------------------------
// fp16 tensor-core GEMM: C[4096,512] = (A @ B^T + bias) * scale
// Block 128m x 64n, BK=64, cp.async double-buffered. 8 warps (4m x 2n).
// ---------------------------------------------------------------------------
template <typename OutT>
__global__ void __launch_bounds__(256, 2) gemm_h(const __half* __restrict__ A,
                                                 const __half* __restrict__ B,
                                                 const float* __restrict__ bias,
                                                 OutT* __restrict__ C,
                                                 float scale) {
    __shared__ __align__(128) char gsm[49152];
    unsigned sb = (unsigned)__cvta_generic_to_shared(gsm);

    int tid = threadIdx.x;
    int w = tid >> 5, lane = tid & 31;
    int t4 = lane >> 2, tm4 = lane & 3;
    unsigned lrow = lane & 15;
    unsigned hi16 = ((lane >> 4) & 1) * 16;
    int wm = (w >> 1) * 32, wn = (w & 1) * 32;
    int m0 = blockIdx.y * 128, n0 = blockIdx.x * 64;

    int srow = tid >> 3, scd = tid & 7;

#pragma unroll
    for (int i = 0; i < 4; i++) {
        int idx = tid + i * 256;
        int row = idx >> 3, cd = idx & 7;
        cpa16(sb + swz(row, cd * 16), A + (m0 + row) * 512 + cd * 8);
    }
#pragma unroll
    for (int i = 0; i < 2; i++) {
        int row = srow + i * 32;
        cpa16(sb + 32768 + swz(row, scd * 16), B + (n0 + row) * 512 + scd * 8);
    }
    cpa_commit();

    float acc[2][4][4] = {};

    for (int it = 0; it < 8; it++) {
        cpa_wait0();
        __syncthreads();
        if (it + 1 < 8) {
            int buf = (it + 1) & 1;
            int k0 = (it + 1) * 64;
#pragma unroll
            for (int i = 0; i < 4; i++) {
                int idx = tid + i * 256;
                int row = idx >> 3, cd = idx & 7;
                cpa16(sb + buf * 16384 + swz(row, cd * 16),
                      A + (m0 + row) * 512 + k0 + cd * 8);
            }
#pragma unroll
            for (int i = 0; i < 2; i++) {
                int row = srow + i * 32;
                cpa16(sb + 32768 + buf * 8192 + swz(row, scd * 16),
                      B + (n0 + row) * 512 + k0 + scd * 8);
            }
            cpa_commit();
        }

        unsigned abase = sb + (it & 1) * 16384;
        unsigned bbase = sb + 32768 + (it & 1) * 8192;
#pragma unroll
        for (int kc = 0; kc < 4; kc++) {
            unsigned af[2][4];
#pragma unroll
            for (int g = 0; g < 2; g++)
                ldsm4(af[g][0], af[g][1], af[g][2], af[g][3],
                      abase + swz(wm + g * 16 + lrow, kc * 32 + hi16));
#pragma unroll
            for (int ng = 0; ng < 2; ng++) {
                unsigned b0, b1, b2, b3;
                ldsm4(b0, b1, b2, b3,
                      bbase + swz(wn + ng * 16 + lrow, kc * 32 + hi16));
                mma16(acc[0][2 * ng], af[0], b0, b2);
                mma16(acc[0][2 * ng + 1], af[0], b1, b3);
                mma16(acc[1][2 * ng], af[1], b0, b2);
                mma16(acc[1][2 * ng + 1], af[1], b1, b3);
            }
        }
    }

#pragma unroll
    for (int g = 0; g < 2; g++) {
        int r0 = m0 + wm + g * 16 + t4;
#pragma unroll
        for (int nt = 0; nt < 4; nt++) {
            int c = n0 + wn + nt * 8 + tm4 * 2;
            float b0 = bias[c], b1 = bias[c + 1];
            float v00 = (acc[g][nt][0] + b0) * scale;
            float v01 = (acc[g][nt][1] + b1) * scale;
            float v10 = (acc[g][nt][2] + b0) * scale;
            float v11 = (acc[g][nt][3] + b1) * scale;
            if constexpr (sizeof(OutT) == 2) {
                *(__half2*)((__half*)C + r0 * 512 + c) = __floats2half2_rn(v00, v01);
                *(__half2*)((__half*)C + (r0 + 8) * 512 + c) = __floats2half2_rn(v10, v11);
            } else {
                *(float2*)((float*)C + r0 * 512 + c) = make_float2(v00, v01);
                *(float2*)((float*)C + (r0 + 8) * 512 + c) = make_float2(v10, v11);
            }
        }
    }
}

// ---------------------------------------------------------------------------
// fp16 flash attention, 3-stage cp.async pipeline, log2-domain softmax,
// ex2.approx.f16x2, row-sums via ones-MMA. Block = 128 q-rows x 1 head.
// smem: 3 stages x 16KB (K @ +0, V @ +8192). Q staged via stage 2, then regs.
// Q pre-scaled by 0.125*log2e in the projection gemm.
// ---------------------------------------------------------------------------
#define STG 16384
#define ASMEM (3 * STG)

__global__ void __launch_bounds__(256, 2) attn_fp16() {
    extern __shared__ char sm[];
    unsigned sb = (unsigned)__cvta_generic_to_shared(sm);
    int tid = threadIdx.x;
    int w = tid >> 5, lane = tid & 31;
    int t4 = lane >> 2, tm4 = lane & 3;
    int qt = blockIdx.x, h = blockIdx.y;

    const __half* Qh = g_q + h * (SQ * DKH);
    const __half* Kh = g_k + h * (SQ * DKH);
    const __half* Vh = g_v + h * (SQ * DKH);

    int srow = tid >> 3, scd = tid & 7;

    // Prologue. G0 = {Q -> stage2, K0/V0 -> stage0}; G1 = {K1/V1 -> stage1}.
#pragma unroll
    for (int i = 0; i < 4; i++) {
        int idx = tid + i * 256;
        int row = idx >> 3, cd = idx & 7;
        cpa16(sb + 2 * STG + swz(row, cd * 16),
              Qh + (qt * 128 + row) * 64 + cd * 8);
    }
#pragma unroll
    for (int i = 0; i < 2; i++) {
        int row = srow + i * 32;
        cpa16(sb + swz(row, scd * 16), Kh + row * 64 + scd * 8);
        cpa16(sb + 8192 + swz(row, scd * 16), Vh + row * 64 + scd * 8);
    }
    cpa_commit();  // G0
#pragma unroll
    for (int i = 0; i < 2; i++) {
        int row = srow + i * 32;
        cpa16(sb + STG + swz(row, scd * 16), Kh + 4096 + row * 64 + scd * 8);
        cpa16(sb + STG + 8192 + swz(row, scd * 16),
              Vh + 4096 + row * 64 + scd * 8);
    }
    cpa_commit();  // G1

    unsigned qrow = w * 16 + (lane & 15);
    unsigned lrow = lane & 15;
    unsigned hi16 = ((lane >> 4) & 1) * 16;

    cpa_wait1();  // G0 done (Q + K0/V0)
    __syncthreads();

    // Q fragments: loop-invariant, register-resident
    unsigned qf[4][4];
#pragma unroll
    for (int kc = 0; kc < 4; kc++)
        ldsm4(qf[kc][0], qf[kc][1], qf[kc][2], qf[kc][3],
              sb + 2 * STG + swz(qrow, kc * 32 + hi16));
    __syncthreads();  // all warps own qf before stage2 is reused

    float o[8][4];
#pragma unroll
    for (int nt = 0; nt < 8; nt++)
#pragma unroll
        for (int j = 0; j < 4; j++) o[nt][j] = 0.f;
    float m0 = -INFINITY, m1 = -INFINITY, l0 = 0.f, l1 = 0.f;

    const unsigned* mrow0 = g_maskbits + (qt * 128 + w * 16 + t4) * 128;
    const unsigned* mrow1 = mrow0 + 8 * 128;
    const unsigned ONES = 0x3C003C00u;

    int stage = 0;  // stage index of iter kt ((kt) % 3)
    for (int kt = 0; kt < 64; kt++) {
        __syncthreads();  // all warps done with buffer (kt+2)%3 (= iter kt-1's)
        int pstage = stage + 2 >= 3 ? stage - 1 : stage + 2;  // (kt+2)%3
        if (kt + 2 < 64) {
#pragma unroll
            for (int i = 0; i < 2; i++) {
                int row = srow + i * 32;
                int gr = (kt + 2) * 64 + row;
                cpa16(sb + pstage * STG + swz(row, scd * 16),
                      Kh + gr * 64 + scd * 8);
                cpa16(sb + pstage * STG + 8192 + swz(row, scd * 16),
                      Vh + gr * 64 + scd * 8);
            }
        }
        cpa_commit();
        cpa_wait2();  // group of iter kt complete (committed 2 iters ago)

        // mask words early (L2 latency hides under S-mma)
        unsigned mw0a = mrow0[kt * 2], mw0b = mrow0[kt * 2 + 1];
        unsigned mw1a = mrow1[kt * 2], mw1b = mrow1[kt * 2 + 1];

        unsigned kbase = sb + stage * STG;
        unsigned vbase = kbase + 8192;

        // S = Q' @ K^T  (log2 units)
        float s[8][4];
#pragma unroll
        for (int nt = 0; nt < 8; nt++)
#pragma unroll
            for (int j = 0; j < 4; j++) s[nt][j] = 0.f;
#pragma unroll
        for (int kc = 0; kc < 4; kc++)
#pragma unroll
            for (int ng = 0; ng < 4; ng++) {
                unsigned b0, b1, b2, b3;
                ldsm4(b0, b1, b2, b3,
                      kbase + swz(ng * 16 + lrow, kc * 32 + hi16));
                mma16(s[2 * ng], qf[kc], b0, b2);
                mma16(s[2 * ng + 1], qf[kc], b1, b3);
            }

        // Mask + row max
        float rmax0 = -INFINITY, rmax1 = -INFINITY;
#pragma unroll
        for (int nt = 0; nt < 8; nt++) {
            int c = nt * 8 + tm4 * 2;
            unsigned w0 = (c & 32) ? mw0b : mw0a;
            unsigned w1 = (c & 32) ? mw1b : mw1a;
            int sh = c & 31;
            if ((w0 >> sh) & 1u) s[nt][0] -= 1e9f;
            if ((w0 >> (sh + 1)) & 1u) s[nt][1] -= 1e9f;
            if ((w1 >> sh) & 1u) s[nt][2] -= 1e9f;
            if ((w1 >> (sh + 1)) & 1u) s[nt][3] -= 1e9f;
            rmax0 = fmaxf(rmax0, fmaxf(s[nt][0], s[nt][1]));
            rmax1 = fmaxf(rmax1, fmaxf(s[nt][2], s[nt][3]));
        }
        rmax0 = fmaxf(rmax0, __shfl_xor_sync(0xffffffffu, rmax0, 1));
        rmax0 = fmaxf(rmax0, __shfl_xor_sync(0xffffffffu, rmax0, 2));
        rmax1 = fmaxf(rmax1, __shfl_xor_sync(0xffffffffu, rmax1, 1));
        rmax1 = fmaxf(rmax1, __shfl_xor_sync(0xffffffffu, rmax1, 2));

        float mn0 = fmaxf(m0, rmax0), mn1 = fmaxf(m1, rmax1);
        float al0 = exp2f(m0 - mn0), al1 = exp2f(m1 - mn1);
        m0 = mn0; m1 = mn1;

        // P = 2^(s - mn), packed f16x2 straight into A-fragment registers
        unsigned pf[4][4];
#pragma unroll
        for (int nt = 0; nt < 8; nt++) {
            int kc = nt >> 1, base = (nt & 1) * 2;
            pf[kc][base] = ex2x2(s[nt][0] - mn0, s[nt][1] - mn0);
            pf[kc][base + 1] = ex2x2(s[nt][2] - mn1, s[nt][3] - mn1);
        }

        // Row sums via ones-MMA (no shuffles; lands on tensor pipe)
        float rs[4] = {0.f, 0.f, 0.f, 0.f};
#pragma unroll
        for (int kc = 0; kc < 4; kc++) mma16(rs, pf[kc], ONES, ONES);

#pragma unroll
        for (int nt = 0; nt < 8; nt++) {
            o[nt][0] *= al0; o[nt][1] *= al0;
            o[nt][2] *= al1; o[nt][3] *= al1;
        }

        // O += P @ V   (V via ldmatrix.trans)
#pragma unroll
        for (int kc = 0; kc < 4; kc++)
#pragma unroll
            for (int ng = 0; ng < 4; ng++) {
                unsigned v0, v1, v2, v3;
                ldsm4t(v0, v1, v2, v3,
                       vbase + swz(kc * 16 + lrow, ng * 32 + hi16));
                mma16(o[2 * ng], pf[kc], v0, v1);
                mma16(o[2 * ng + 1], pf[kc], v2, v3);
            }

        l0 = l0 * al0 + rs[0];
        l1 = l1 * al1 + rs[2];

        stage = stage + 1 >= 3 ? 0 : stage + 1;
    }

    // Epilogue: normalize, write fp16 attn[s', h*64 + d]
    float inv0 = 1.f / l0, inv1 = 1.f / l1;
    int r0 = qt * 128 + w * 16 + t4;
    int r1 = r0 + 8;
#pragma unroll
    for (int nt = 0; nt < 8; nt++) {
        int c = h * 64 + nt * 8 + tm4 * 2;
        *(__half2*)&g_attnh[r0 * 512 + c] =
            __floats2half2_rn(o[nt][0] * inv0, o[nt][1] * inv0);
        *(__half2*)&g_attnh[r1 * 512 + c] =
            __floats2half2_rn(o[nt][2] * inv1, o[nt][3] * inv1);
    }
}

// ---------------------------------------------------------------------------
extern "C" void kernel_launch(void* const* d_in, const int* in_sizes, int n_in,
                              void* d_out, int out_size) {
    const float* x    = (const float*)d_in[0];
    const int*   mask = (const int*)d_in[1];
    const float* wq_w = (const float*)d_in[2];
    const float* wq_b = (const float*)d_in[3];
    const float* wk_w = (const float*)d_in[4];
    const float* wk_b = (const float*)d_in[5];
    const float* wv_w = (const float*)d_in[6];
    const float* wv_b = (const float*)d_in[7];
    const float* dw   = (const float*)d_in[8];
    const float* db   = (const float*)d_in[9];
    float* out = (float*)d_out;

    __half *qp, *kp, *vp, *xp, *ah, *wqh, *wkh, *wvh, *wdh;
    cudaGetSymbolAddress((void**)&qp, g_q);
    cudaGetSymbolAddress((void**)&kp, g_k);
    cudaGetSymbolAddress((void**)&vp, g_v);
    cudaGetSymbolAddress((void**)&xp, g_xh);
    cudaGetSymbolAddress((void**)&ah, g_attnh);
    cudaGetSymbolAddress((void**)&wqh, g_wqh);
    cudaGetSymbolAddress((void**)&wkh, g_wkh);
    cudaGetSymbolAddress((void**)&wvh, g_wvh);
    cudaGetSymbolAddress((void**)&wdh, g_wdh);

    cudaFuncSetAttribute(attn_fp16,
                         cudaFuncAttributeMaxDynamicSharedMemorySize, ASMEM);

    const float QSCALE = 0.125f * 1.44269504f;  // fold 1/sqrt(dk) and log2e

    mask_pack_kernel<<<SQ * SQ / 32 / 8, 256>>>(mask);
    cvt_kernel<<<3072, 256>>>(x, wq_w, wk_w, wv_w, dw);

    dim3 gg(512 / 64, 4096 / 128);
    gemm_h<__half><<<gg, 256>>>(xp, wqh, wq_b, qp, QSCALE);
    gemm_h<__half><<<gg, 256>>>(xp, wkh, wk_b, kp, 1.0f);
    gemm_h<__half><<<gg, 256>>>(xp, wvh, wv_b, vp, 1.0f);

    attn_fp16<<<dim3(32, 8), 256, ASMEM>>>();

    gemm_h<float><<<gg, 256>>>(ah, wdh, db, out, 1.0f);
}